// round 3
// baseline (speedup 1.0000x reference)
#include <cuda_runtime.h>

#define HW   16384        // 128*128
#define CIN  256
#define NB   4
#define WDIM 128

// Scratch (allocation-free rule: __device__ globals)
__device__ float g_value[(size_t)NB * 256 * HW];   // 64 MB
__device__ float g_hbuf [(size_t)NB * 256 * HW];   // 64 MB
__device__ float g_flow [(size_t)NB * 64  * HW];   // 16 MB

// ---------------------------------------------------------------------------
// Fused conv GEMM: computes value = wv@u + bv  (mblk 0,1)
//                  and      h    = relu(w1@u + b1)  (mblk 2,3)
// Tile: BM=128, BN=128, BK=16, 256 threads, 8x8 per-thread microtile.
// ---------------------------------------------------------------------------
__global__ __launch_bounds__(256)
void conv_gemm_kernel(const float* __restrict__ u,
                      const float* __restrict__ w1, const float* __restrict__ b1,
                      const float* __restrict__ wv, const float* __restrict__ bv)
{
    __shared__ float As[2][16][132];   // [k][m], padded
    __shared__ float Bs[2][16][128];   // [k][n]

    const int tid  = threadIdx.x;
    const int bz   = blockIdx.z;
    const int nblk = blockIdx.x;          // pixel tile
    const int mblk = blockIdx.y;          // 0..3
    const bool is_h = (mblk >= 2);
    const float* W  = is_h ? w1 : wv;
    const int mrow0 = (mblk & 1) * 128;   // row offset inside the 256-row weight
    const float* U  = u + (size_t)bz * CIN * HW + nblk * 128;

    // A-load mapping: 128 rows x 16 k, 2 float4 per thread
    const int ar = tid >> 2;              // 0..63
    const int ac = (tid & 3) * 4;         // 0,4,8,12
    // B-load mapping: 16 k x 128 n, 2 float4 per thread
    const int bk = tid >> 5;              // 0..7
    const int bn = (tid & 31) * 4;        // 0..124

    const int tx = tid & 15;
    const int ty = tid >> 4;

    float acc[8][8];
#pragma unroll
    for (int i = 0; i < 8; i++)
#pragma unroll
        for (int j = 0; j < 8; j++) acc[i][j] = 0.f;

    float4 aR0, aR1, bR0, bR1;

    // prologue: tile 0
    {
        const float* Ap = W + (size_t)(mrow0 + ar) * CIN + ac;
        aR0 = *(const float4*)Ap;
        aR1 = *(const float4*)(Ap + (size_t)64 * CIN);
        const float* Bp = U + (size_t)bk * HW + bn;
        bR0 = *(const float4*)Bp;
        bR1 = *(const float4*)(Bp + (size_t)8 * HW);
    }
    {
        As[0][ac+0][ar] = aR0.x; As[0][ac+1][ar] = aR0.y;
        As[0][ac+2][ar] = aR0.z; As[0][ac+3][ar] = aR0.w;
        As[0][ac+0][ar+64] = aR1.x; As[0][ac+1][ar+64] = aR1.y;
        As[0][ac+2][ar+64] = aR1.z; As[0][ac+3][ar+64] = aR1.w;
        *(float4*)&Bs[0][bk  ][bn] = bR0;
        *(float4*)&Bs[0][bk+8][bn] = bR1;
    }
    __syncthreads();

    int buf = 0;
#pragma unroll 1
    for (int kt = 0; kt < 16; kt++) {
        if (kt + 1 < 16) {
            const int k0 = (kt + 1) * 16;
            const float* Ap = W + (size_t)(mrow0 + ar) * CIN + k0 + ac;
            aR0 = *(const float4*)Ap;
            aR1 = *(const float4*)(Ap + (size_t)64 * CIN);
            const float* Bp = U + (size_t)(k0 + bk) * HW + bn;
            bR0 = *(const float4*)Bp;
            bR1 = *(const float4*)(Bp + (size_t)8 * HW);
        }
#pragma unroll
        for (int kk = 0; kk < 16; kk++) {
            float a[8], bb[8];
            *(float4*)&a[0]  = *(const float4*)&As[buf][kk][ty * 4];
            *(float4*)&a[4]  = *(const float4*)&As[buf][kk][64 + ty * 4];
            *(float4*)&bb[0] = *(const float4*)&Bs[buf][kk][tx * 4];
            *(float4*)&bb[4] = *(const float4*)&Bs[buf][kk][64 + tx * 4];
#pragma unroll
            for (int i = 0; i < 8; i++)
#pragma unroll
                for (int j = 0; j < 8; j++)
                    acc[i][j] = fmaf(a[i], bb[j], acc[i][j]);
        }
        if (kt + 1 < 16) {
            const int nb2 = buf ^ 1;
            As[nb2][ac+0][ar] = aR0.x; As[nb2][ac+1][ar] = aR0.y;
            As[nb2][ac+2][ar] = aR0.z; As[nb2][ac+3][ar] = aR0.w;
            As[nb2][ac+0][ar+64] = aR1.x; As[nb2][ac+1][ar+64] = aR1.y;
            As[nb2][ac+2][ar+64] = aR1.z; As[nb2][ac+3][ar+64] = aR1.w;
            *(float4*)&Bs[nb2][bk  ][bn] = bR0;
            *(float4*)&Bs[nb2][bk+8][bn] = bR1;
            buf = nb2;
            __syncthreads();
        }
    }

    // Epilogue
    const int pix0 = nblk * 128;
    float* outbuf = is_h ? g_hbuf : g_value;
    const float* bias = is_h ? b1 : bv;
    const size_t base = (size_t)bz * 256 * HW;

#pragma unroll
    for (int i = 0; i < 8; i++) {
        const int mi = mrow0 + ((i < 4) ? (ty * 4 + i) : (64 + ty * 4 + (i - 4)));
        const float bb = bias[mi];
        float r[8];
#pragma unroll
        for (int j = 0; j < 8; j++) {
            float v = acc[i][j] + bb;
            if (is_h) v = fmaxf(v, 0.f);
            r[j] = v;
        }
        float* op = outbuf + base + (size_t)mi * HW + pix0;
        *(float4*)&op[tx * 4]      = *(float4*)&r[0];
        *(float4*)&op[64 + tx * 4] = *(float4*)&r[4];
    }
}

// ---------------------------------------------------------------------------
// Flow GEMM: flow = w2 @ h + b2.  BM=64, BN=128, BK=16, 256 threads, 4x8 tile.
// ---------------------------------------------------------------------------
__global__ __launch_bounds__(256)
void flow_gemm_kernel(const float* __restrict__ w2, const float* __restrict__ b2)
{
    __shared__ float As[2][16][68];
    __shared__ float Bs[2][16][128];

    const int tid  = threadIdx.x;
    const int bz   = blockIdx.z;
    const int nblk = blockIdx.x;
    const float* U = g_hbuf + (size_t)bz * 256 * HW + nblk * 128;

    const int ar = tid >> 2;              // 0..63
    const int ac = (tid & 3) * 4;
    const int bk = tid >> 5;
    const int bn = (tid & 31) * 4;
    const int tx = tid & 15;
    const int ty = tid >> 4;              // 0..15 -> rows ty*4..+3

    float acc[4][8];
#pragma unroll
    for (int i = 0; i < 4; i++)
#pragma unroll
        for (int j = 0; j < 8; j++) acc[i][j] = 0.f;

    float4 aR0, bR0, bR1;
    {
        aR0 = *(const float4*)(w2 + (size_t)ar * CIN + ac);
        const float* Bp = U + (size_t)bk * HW + bn;
        bR0 = *(const float4*)Bp;
        bR1 = *(const float4*)(Bp + (size_t)8 * HW);
    }
    {
        As[0][ac+0][ar] = aR0.x; As[0][ac+1][ar] = aR0.y;
        As[0][ac+2][ar] = aR0.z; As[0][ac+3][ar] = aR0.w;
        *(float4*)&Bs[0][bk  ][bn] = bR0;
        *(float4*)&Bs[0][bk+8][bn] = bR1;
    }
    __syncthreads();

    int buf = 0;
#pragma unroll 1
    for (int kt = 0; kt < 16; kt++) {
        if (kt + 1 < 16) {
            const int k0 = (kt + 1) * 16;
            aR0 = *(const float4*)(w2 + (size_t)ar * CIN + k0 + ac);
            const float* Bp = U + (size_t)(k0 + bk) * HW + bn;
            bR0 = *(const float4*)Bp;
            bR1 = *(const float4*)(Bp + (size_t)8 * HW);
        }
#pragma unroll
        for (int kk = 0; kk < 16; kk++) {
            float a[4], bb[8];
            *(float4*)&a[0]  = *(const float4*)&As[buf][kk][ty * 4];
            *(float4*)&bb[0] = *(const float4*)&Bs[buf][kk][tx * 4];
            *(float4*)&bb[4] = *(const float4*)&Bs[buf][kk][64 + tx * 4];
#pragma unroll
            for (int i = 0; i < 4; i++)
#pragma unroll
                for (int j = 0; j < 8; j++)
                    acc[i][j] = fmaf(a[i], bb[j], acc[i][j]);
        }
        if (kt + 1 < 16) {
            const int nb2 = buf ^ 1;
            As[nb2][ac+0][ar] = aR0.x; As[nb2][ac+1][ar] = aR0.y;
            As[nb2][ac+2][ar] = aR0.z; As[nb2][ac+3][ar] = aR0.w;
            *(float4*)&Bs[nb2][bk  ][bn] = bR0;
            *(float4*)&Bs[nb2][bk+8][bn] = bR1;
            buf = nb2;
            __syncthreads();
        }
    }

    const int pix0 = nblk * 128;
    const size_t base = (size_t)bz * 64 * HW;
#pragma unroll
    for (int i = 0; i < 4; i++) {
        const int mi = ty * 4 + i;
        const float bb = b2[mi];
        float r[8];
#pragma unroll
        for (int j = 0; j < 8; j++) r[j] = acc[i][j] + bb;
        float* op = g_flow + base + (size_t)mi * HW + pix0;
        *(float4*)&op[tx * 4]      = *(float4*)&r[0];
        *(float4*)&op[64 + tx * 4] = *(float4*)&r[4];
    }
}

// ---------------------------------------------------------------------------
// Gather: bilinear grid-sample with zeros padding, align_corners=True.
// One thread per (x), block per (y), grid.y per (b*32+head). 8 channels/thread.
// ---------------------------------------------------------------------------
__global__ __launch_bounds__(128)
void warp_gather_kernel(float* __restrict__ out)
{
    const int x  = threadIdx.x;          // 0..127
    const int y  = blockIdx.x;           // 0..127
    const int bh = blockIdx.y;           // 0..127
    const int b  = bh >> 5;
    const int head = bh & 31;

    const float* fb = g_flow + ((size_t)b * 64 + head * 2) * HW + y * WDIM + x;
    const float fx = fb[0];
    const float fy = fb[HW];

    const float gx = fmaf((float)x, 2.f / 127.f, -1.f) + fx;
    const float gy = fmaf((float)y, 2.f / 127.f, -1.f) + fy;
    const float ix = (gx + 1.f) * 63.5f;
    const float iy = (gy + 1.f) * 63.5f;

    const float x0f = floorf(ix), y0f = floorf(iy);
    const float dx = ix - x0f, dy = iy - y0f;
    const int x0 = (int)x0f, y0 = (int)y0f;
    const int x1 = x0 + 1,   y1 = y0 + 1;

    const bool vx0 = (x0 >= 0) & (x0 < WDIM);
    const bool vx1 = (x1 >= 0) & (x1 < WDIM);
    const bool vy0 = (y0 >= 0) & (y0 < WDIM);
    const bool vy1 = (y1 >= 0) & (y1 < WDIM);

    const int x0c = min(max(x0, 0), WDIM - 1);
    const int x1c = min(max(x1, 0), WDIM - 1);
    const int y0c = min(max(y0, 0), WDIM - 1);
    const int y1c = min(max(y1, 0), WDIM - 1);

    const float w00 = (1.f - dx) * (1.f - dy) * (float)(vx0 & vy0);
    const float w01 = dx * (1.f - dy)         * (float)(vx1 & vy0);
    const float w10 = (1.f - dx) * dy         * (float)(vx0 & vy1);
    const float w11 = dx * dy                 * (float)(vx1 & vy1);

    const int p00 = y0c * WDIM + x0c;
    const int p01 = y0c * WDIM + x1c;
    const int p10 = y1c * WDIM + x0c;
    const int p11 = y1c * WDIM + x1c;

    const float* vb = g_value + ((size_t)b * 256 + head * 8) * HW;
    float* ob = out + ((size_t)b * 256 + head * 8) * HW + y * WDIM + x;

#pragma unroll
    for (int ci = 0; ci < 8; ci++) {
        const float* v = vb + (size_t)ci * HW;
        float r = w00 * v[p00] + w01 * v[p01] + w10 * v[p10] + w11 * v[p11];
        ob[(size_t)ci * HW] = r;
    }
}

// ---------------------------------------------------------------------------
extern "C" void kernel_launch(void* const* d_in, const int* in_sizes, int n_in,
                              void* d_out, int out_size)
{
    const float* u  = (const float*)d_in[0];
    const float* w1 = (const float*)d_in[1];
    const float* b1 = (const float*)d_in[2];
    const float* w2 = (const float*)d_in[3];
    const float* b2 = (const float*)d_in[4];
    const float* wv = (const float*)d_in[5];
    const float* bv = (const float*)d_in[6];
    float* out = (float*)d_out;

    conv_gemm_kernel<<<dim3(128, 4, NB), 256>>>(u, w1, b1, wv, bv);
    flow_gemm_kernel<<<dim3(128, 1, NB), 256>>>(w2, b2);
    warp_gather_kernel<<<dim3(128, 128), 128>>>(out);
}

// round 6
// speedup vs baseline: 1.2487x; 1.2487x over previous
#include <cuda_runtime.h>
#include <cuda_bf16.h>
#include <cstdint>

#define HW   16384
#define NB   4
#define WDIM 128

// ---------------- scratch (__device__ globals; no allocs allowed) ----------
__device__ __nv_bfloat16 g_Ahi[512 * 256];                 // [wv; w1] hi, row-major [m][k]
__device__ __nv_bfloat16 g_Alo[512 * 256];
__device__ __nv_bfloat16 g_W2hi[128 * 256];                // w2 padded to 128 rows
__device__ __nv_bfloat16 g_W2lo[128 * 256];
__device__ __nv_bfloat16 g_Bthi[(size_t)NB * HW * 256];    // uT hi  [b][p][c]
__device__ __nv_bfloat16 g_Btlo[(size_t)NB * HW * 256];
__device__ __nv_bfloat16 g_Hmhi[(size_t)NB * 256 * HW];    // h hi   [b][c][p]
__device__ __nv_bfloat16 g_Hmlo[(size_t)NB * 256 * HW];
__device__ __nv_bfloat16 g_Hthi[(size_t)NB * HW * 256];    // hT hi  [b][p][c]
__device__ __nv_bfloat16 g_Htlo[(size_t)NB * HW * 256];
__device__ float g_value[(size_t)NB * 256 * HW];
__device__ float g_flow [(size_t)NB * 64 * HW];

// ---------------- helpers ---------------------------------------------------
__device__ __forceinline__ uint32_t smem_u32(const void* p) {
    uint32_t a;
    asm("{ .reg .u64 t; cvta.to.shared.u64 t, %1; cvt.u32.u64 %0, t; }" : "=r"(a) : "l"(p));
    return a;
}
__device__ __forceinline__ void ldsm_x4(uint32_t* r, uint32_t addr) {
    asm volatile("ldmatrix.sync.aligned.m8n8.x4.shared.b16 {%0,%1,%2,%3}, [%4];"
                 : "=r"(r[0]), "=r"(r[1]), "=r"(r[2]), "=r"(r[3]) : "r"(addr));
}
__device__ __forceinline__ void ldsm_x2(uint32_t* r, uint32_t addr) {
    asm volatile("ldmatrix.sync.aligned.m8n8.x2.shared.b16 {%0,%1}, [%2];"
                 : "=r"(r[0]), "=r"(r[1]) : "r"(addr));
}
__device__ __forceinline__ void mma16816(float* c, const uint32_t* a, const uint32_t* b) {
    asm volatile("mma.sync.aligned.m16n8k16.row.col.f32.bf16.bf16.f32 "
                 "{%0,%1,%2,%3}, {%4,%5,%6,%7}, {%8,%9}, {%0,%1,%2,%3};"
                 : "+f"(c[0]), "+f"(c[1]), "+f"(c[2]), "+f"(c[3])
                 : "r"(a[0]), "r"(a[1]), "r"(a[2]), "r"(a[3]), "r"(b[0]), "r"(b[1]));
}

// ---------------------------------------------------------------------------
__global__ void prep_weights(const float* __restrict__ w1, const float* __restrict__ wv,
                             const float* __restrict__ w2)
{
    int idx = blockIdx.x * 256 + threadIdx.x;
    if (blockIdx.x < 512) {
        int r = idx >> 8, k = idx & 255;
        float x = (r < 256) ? wv[r * 256 + k] : w1[(r - 256) * 256 + k];
        __nv_bfloat16 h = __float2bfloat16_rn(x);
        g_Ahi[idx] = h;
        g_Alo[idx] = __float2bfloat16_rn(x - __bfloat162float(h));
    } else {
        int i2 = idx - 512 * 256;
        int r = i2 >> 8, k = i2 & 255;
        float x = (r < 64) ? w2[r * 256 + k] : 0.f;
        __nv_bfloat16 h = __float2bfloat16_rn(x);
        g_W2hi[i2] = h;
        g_W2lo[i2] = __float2bfloat16_rn(x - __bfloat162float(h));
    }
}

// u [b][c][p] fp32 -> uT hi/lo [b][p][c] bf16
__global__ __launch_bounds__(256) void transpose_u(const float* __restrict__ u)
{
    __shared__ float ts[32][33];
    const int b = blockIdx.z, c0 = blockIdx.y * 32, p0 = blockIdx.x * 32;
    const int tx = threadIdx.x, ty = threadIdx.y;
    const float* up = u + ((size_t)b * 256 + c0) * HW + p0;
#pragma unroll
    for (int i = 0; i < 4; i++)
        ts[ty + i * 8][tx] = up[(size_t)(ty + i * 8) * HW + tx];
    __syncthreads();
#pragma unroll
    for (int i = 0; i < 4; i++) {
        const int p = ty + i * 8;
        float x = ts[tx][p];
        __nv_bfloat16 h = __float2bfloat16_rn(x);
        size_t o = ((size_t)b * HW + p0 + p) * 256 + c0 + tx;
        g_Bthi[o] = h;
        g_Btlo[o] = __float2bfloat16_rn(x - __bfloat162float(h));
    }
}

// h hi/lo [b][c][p] -> hT hi/lo [b][p][c]
__global__ __launch_bounds__(256) void transpose_h()
{
    __shared__ __nv_bfloat16 th[32][34];
    __shared__ __nv_bfloat16 tl[32][34];
    const int b = blockIdx.z, c0 = blockIdx.y * 32, p0 = blockIdx.x * 32;
    const int tx = threadIdx.x, ty = threadIdx.y;
    const __nv_bfloat16* sh = g_Hmhi + ((size_t)b * 256 + c0) * HW + p0;
    const __nv_bfloat16* sl = g_Hmlo + ((size_t)b * 256 + c0) * HW + p0;
#pragma unroll
    for (int i = 0; i < 4; i++) {
        th[ty + i * 8][tx] = sh[(size_t)(ty + i * 8) * HW + tx];
        tl[ty + i * 8][tx] = sl[(size_t)(ty + i * 8) * HW + tx];
    }
    __syncthreads();
#pragma unroll
    for (int i = 0; i < 4; i++) {
        const int p = ty + i * 8;
        size_t o = ((size_t)b * HW + p0 + p) * 256 + c0 + tx;
        g_Hthi[o] = th[tx][p];
        g_Htlo[o] = tl[tx][p];
    }
}

// ---------------------------------------------------------------------------
// mma.sync split-bf16 GEMM.  MODE 0: [value;h](m=512) = [wv;w1] @ u.
// MODE 1: flow(m=64, padded 128) = w2 @ h.
// BM=128, BN=128, BK=32.  8 warps in 2x4 grid; warp tile 64x32.
// smem pitch 40 bf16 (80B) -> conflict-free ldmatrix.
// ---------------------------------------------------------------------------
#define PITCH 40

template <int MODE>
__global__ __launch_bounds__(256, 2) void gemm_kernel(const float* __restrict__ bias_a,
                                                      const float* __restrict__ bias_b)
{
    __shared__ __nv_bfloat16 As[2][128 * PITCH];   // hi, lo : [m][k] pitch 40
    __shared__ __nv_bfloat16 Bs[2][128 * PITCH];   // hi, lo : [n][k] pitch 40

    const int tid = threadIdx.x, lane = tid & 31, wid = tid >> 5;
    const int wm = wid >> 2, wn = wid & 3;
    const int ntile = blockIdx.x, mtile = blockIdx.y, b = blockIdx.z;
    const int n0 = ntile * 128;

    const __nv_bfloat16* Agh = (MODE == 0) ? g_Ahi + (size_t)mtile * 128 * 256 : g_W2hi;
    const __nv_bfloat16* Agl = (MODE == 0) ? g_Alo + (size_t)mtile * 128 * 256 : g_W2lo;
    const __nv_bfloat16* Bgh = ((MODE == 0) ? g_Bthi : g_Hthi) + ((size_t)b * HW + n0) * 256;
    const __nv_bfloat16* Bgl = ((MODE == 0) ? g_Btlo : g_Htlo) + ((size_t)b * HW + n0) * 256;

    const uint32_t uA0 = smem_u32(As[0]), uA1 = smem_u32(As[1]);
    const uint32_t uB0 = smem_u32(Bs[0]), uB1 = smem_u32(Bs[1]);

    float acc[4][4][4];
#pragma unroll
    for (int mi = 0; mi < 4; mi++)
#pragma unroll
        for (int ni = 0; ni < 4; ni++)
#pragma unroll
            for (int e = 0; e < 4; e++) acc[mi][ni][e] = 0.f;

#pragma unroll 1
    for (int kt = 0; kt < 8; kt++) {
        const int k0 = kt * 32;
        __syncthreads();
#pragma unroll
        for (int q = tid; q < 512; q += 256) {
            const int r = q >> 2, c8 = (q & 3) * 8;
            const int d = r * PITCH + c8;
            const size_t s = (size_t)r * 256 + k0 + c8;
            *(uint4*)&As[0][d] = *(const uint4*)&Agh[s];
            *(uint4*)&As[1][d] = *(const uint4*)&Agl[s];
            *(uint4*)&Bs[0][d] = *(const uint4*)&Bgh[s];
            *(uint4*)&Bs[1][d] = *(const uint4*)&Bgl[s];
        }
        __syncthreads();

#pragma unroll
        for (int s = 0; s < 2; s++) {
            uint32_t ah[4][4], al[4][4];
            const uint32_t arow = (uint32_t)(wm * 64 + (lane & 15));
            const uint32_t aoff = 2u * (arow * PITCH + s * 16 + (lane >> 4) * 8);
#pragma unroll
            for (int mi = 0; mi < 4; mi++) {
                const uint32_t o = aoff + 2u * (mi * 16 * PITCH);
                ldsm_x4(ah[mi], uA0 + o);
                ldsm_x4(al[mi], uA1 + o);
            }
            const uint32_t brow = (uint32_t)(wn * 32 + (lane & 7));
            const uint32_t boff = 2u * (brow * PITCH + s * 16 + ((lane >> 3) & 1) * 8);
#pragma unroll
            for (int ni = 0; ni < 4; ni++) {
                const uint32_t o = boff + 2u * (ni * 8 * PITCH);
                uint32_t bh[2], bl[2];
                ldsm_x2(bh, uB0 + o);
                ldsm_x2(bl, uB1 + o);
#pragma unroll
                for (int mi = 0; mi < 4; mi++) {
                    mma16816(acc[mi][ni], ah[mi], bh);
                    mma16816(acc[mi][ni], ah[mi], bl);
                    mma16816(acc[mi][ni], al[mi], bh);
                }
            }
        }
    }

    // ---------------- epilogue ----------------
    const int qr = lane >> 2, qc = (lane & 3) * 2;

    if (MODE == 1) {
        if (wm == 1) return;                      // rows 64..127 are padding
#pragma unroll
        for (int mi = 0; mi < 4; mi++) {
            const int m0 = mi * 16 + qr;          // < 64
            const float b0f = bias_a[m0], b1f = bias_a[m0 + 8];
            float* o0 = g_flow + ((size_t)b * 64 + m0) * HW + n0;
            float* o1 = o0 + (size_t)8 * HW;
#pragma unroll
            for (int ni = 0; ni < 4; ni++) {
                const int n = wn * 32 + ni * 8 + qc;
                float2 v0 = {acc[mi][ni][0] + b0f, acc[mi][ni][1] + b0f};
                float2 v1 = {acc[mi][ni][2] + b1f, acc[mi][ni][3] + b1f};
                *(float2*)&o0[n] = v0;
                *(float2*)&o1[n] = v1;
            }
        }
    } else if (mtile < 2) {
#pragma unroll
        for (int mi = 0; mi < 4; mi++) {
            const int c = mtile * 128 + wm * 64 + mi * 16 + qr;
            const float b0f = bias_b[c], b1f = bias_b[c + 8];
            float* o0 = g_value + ((size_t)b * 256 + c) * HW + n0;
            float* o1 = o0 + (size_t)8 * HW;
#pragma unroll
            for (int ni = 0; ni < 4; ni++) {
                const int n = wn * 32 + ni * 8 + qc;
                float2 v0 = {acc[mi][ni][0] + b0f, acc[mi][ni][1] + b0f};
                float2 v1 = {acc[mi][ni][2] + b1f, acc[mi][ni][3] + b1f};
                *(float2*)&o0[n] = v0;
                *(float2*)&o1[n] = v1;
            }
        }
    } else {
#pragma unroll
        for (int mi = 0; mi < 4; mi++) {
            const int c = (mtile - 2) * 128 + wm * 64 + mi * 16 + qr;
            const float b0f = bias_a[c], b1f = bias_a[c + 8];
            __nv_bfloat16* oh0 = g_Hmhi + ((size_t)b * 256 + c) * HW + n0;
            __nv_bfloat16* ol0 = g_Hmlo + ((size_t)b * 256 + c) * HW + n0;
#pragma unroll
            for (int ni = 0; ni < 4; ni++) {
                const int n = wn * 32 + ni * 8 + qc;
#pragma unroll
                for (int half = 0; half < 2; half++) {
                    const float bb = half ? b1f : b0f;
                    float x0 = fmaxf(acc[mi][ni][half * 2 + 0] + bb, 0.f);
                    float x1 = fmaxf(acc[mi][ni][half * 2 + 1] + bb, 0.f);
                    __nv_bfloat16 h0 = __float2bfloat16_rn(x0);
                    __nv_bfloat16 h1 = __float2bfloat16_rn(x1);
                    __nv_bfloat162 hh, ll;
                    hh.x = h0; hh.y = h1;
                    ll.x = __float2bfloat16_rn(x0 - __bfloat162float(h0));
                    ll.y = __float2bfloat16_rn(x1 - __bfloat162float(h1));
                    const size_t off = (size_t)(half * 8) * HW + n;
                    *(__nv_bfloat162*)&oh0[off] = hh;
                    *(__nv_bfloat162*)&ol0[off] = ll;
                }
            }
        }
    }
}

// ---------------------------------------------------------------------------
__global__ __launch_bounds__(128)
void warp_gather_kernel(float* __restrict__ out)
{
    const int x = threadIdx.x, y = blockIdx.x, bh = blockIdx.y;
    const int b = bh >> 5, head = bh & 31;

    const float* fb = g_flow + ((size_t)b * 64 + head * 2) * HW + y * WDIM + x;
    const float fx = fb[0];
    const float fy = fb[HW];

    const float gx = fmaf((float)x, 2.f / 127.f, -1.f) + fx;
    const float gy = fmaf((float)y, 2.f / 127.f, -1.f) + fy;
    const float ix = (gx + 1.f) * 63.5f;
    const float iy = (gy + 1.f) * 63.5f;

    const float x0f = floorf(ix), y0f = floorf(iy);
    const float dx = ix - x0f, dy = iy - y0f;
    const int x0 = (int)x0f, y0 = (int)y0f;
    const int x1 = x0 + 1,   y1 = y0 + 1;

    const bool vx0 = (x0 >= 0) & (x0 < WDIM);
    const bool vx1 = (x1 >= 0) & (x1 < WDIM);
    const bool vy0 = (y0 >= 0) & (y0 < WDIM);
    const bool vy1 = (y1 >= 0) & (y1 < WDIM);

    const int x0c = min(max(x0, 0), WDIM - 1);
    const int x1c = min(max(x1, 0), WDIM - 1);
    const int y0c = min(max(y0, 0), WDIM - 1);
    const int y1c = min(max(y1, 0), WDIM - 1);

    const float w00 = (1.f - dx) * (1.f - dy) * (float)(vx0 & vy0);
    const float w01 = dx * (1.f - dy)         * (float)(vx1 & vy0);
    const float w10 = (1.f - dx) * dy         * (float)(vx0 & vy1);
    const float w11 = dx * dy                 * (float)(vx1 & vy1);

    const int p00 = y0c * WDIM + x0c;
    const int p01 = y0c * WDIM + x1c;
    const int p10 = y1c * WDIM + x0c;
    const int p11 = y1c * WDIM + x1c;

    const float* vb = g_value + ((size_t)b * 256 + head * 8) * HW;
    float* ob = out + ((size_t)b * 256 + head * 8) * HW + y * WDIM + x;

#pragma unroll
    for (int ci = 0; ci < 8; ci++) {
        const float* v = vb + (size_t)ci * HW;
        ob[(size_t)ci * HW] = w00 * v[p00] + w01 * v[p01] + w10 * v[p10] + w11 * v[p11];
    }
}

// ---------------------------------------------------------------------------
extern "C" void kernel_launch(void* const* d_in, const int* in_sizes, int n_in,
                              void* d_out, int out_size)
{
    const float* u  = (const float*)d_in[0];
    const float* w1 = (const float*)d_in[1];
    const float* b1 = (const float*)d_in[2];
    const float* w2 = (const float*)d_in[3];
    const float* b2 = (const float*)d_in[4];
    const float* wv = (const float*)d_in[5];
    const float* bv = (const float*)d_in[6];
    float* out = (float*)d_out;

    prep_weights<<<640, 256>>>(w1, wv, w2);
    transpose_u<<<dim3(512, 8, NB), dim3(32, 8)>>>(u);
    gemm_kernel<0><<<dim3(128, 4, NB), 256>>>(b1, bv);
    transpose_h<<<dim3(512, 8, NB), dim3(32, 8)>>>();
    gemm_kernel<1><<<dim3(128, 1, NB), 256>>>(b2, nullptr);
    warp_gather_kernel<<<dim3(128, 128), 128>>>(out);
}

// round 7
// speedup vs baseline: 1.6075x; 1.2873x over previous
#include <cuda_runtime.h>
#include <cuda_bf16.h>
#include <cstdint>

#define HW   16384
#define NB   4
#define WDIM 128

// ---------------- scratch (__device__ globals) ------------------------------
__device__ __nv_bfloat16 g_Ahi[512 * 256];                 // [wv; w1] hi, [m][k]
__device__ __nv_bfloat16 g_Alo[512 * 256];
__device__ __nv_bfloat16 g_W2hi[128 * 256];                // w2 (64 rows used)
__device__ __nv_bfloat16 g_W2lo[128 * 256];
__device__ __nv_bfloat16 g_Uhi[(size_t)NB * 256 * HW];     // u hi [b][c][p]
__device__ __nv_bfloat16 g_Ulo[(size_t)NB * 256 * HW];
__device__ __nv_bfloat16 g_Hmhi[(size_t)NB * 256 * HW];    // h hi [b][c][p]
__device__ __nv_bfloat16 g_Hmlo[(size_t)NB * 256 * HW];
__device__ float g_value[(size_t)NB * 256 * HW];
__device__ float g_flow [(size_t)NB * 64 * HW];

// ---------------- helpers ---------------------------------------------------
__device__ __forceinline__ uint32_t smem_u32(const void* p) {
    uint32_t a;
    asm("{ .reg .u64 t; cvta.to.shared.u64 t, %1; cvt.u32.u64 %0, t; }" : "=r"(a) : "l"(p));
    return a;
}
__device__ __forceinline__ void ldsm_x4(uint32_t* r, uint32_t addr) {
    asm volatile("ldmatrix.sync.aligned.m8n8.x4.shared.b16 {%0,%1,%2,%3}, [%4];"
                 : "=r"(r[0]), "=r"(r[1]), "=r"(r[2]), "=r"(r[3]) : "r"(addr));
}
__device__ __forceinline__ void ldsm_x2t(uint32_t* r, uint32_t addr) {
    asm volatile("ldmatrix.sync.aligned.m8n8.x2.trans.shared.b16 {%0,%1}, [%2];"
                 : "=r"(r[0]), "=r"(r[1]) : "r"(addr));
}
__device__ __forceinline__ void mma16816(float* c, const uint32_t* a, const uint32_t* b) {
    asm volatile("mma.sync.aligned.m16n8k16.row.col.f32.bf16.bf16.f32 "
                 "{%0,%1,%2,%3}, {%4,%5,%6,%7}, {%8,%9}, {%0,%1,%2,%3};"
                 : "+f"(c[0]), "+f"(c[1]), "+f"(c[2]), "+f"(c[3])
                 : "r"(a[0]), "r"(a[1]), "r"(a[2]), "r"(a[3]), "r"(b[0]), "r"(b[1]));
}
__device__ __forceinline__ void cpa16(uint32_t dst, const void* src) {
    asm volatile("cp.async.cg.shared.global [%0], [%1], 16;" :: "r"(dst), "l"(src));
}
#define CP_COMMIT() asm volatile("cp.async.commit_group;" ::: "memory")
#define CP_WAIT0()  asm volatile("cp.async.wait_group 0;" ::: "memory")

// ---------------------------------------------------------------------------
__global__ void prep_weights(const float* __restrict__ w1, const float* __restrict__ wv,
                             const float* __restrict__ w2)
{
    int idx = blockIdx.x * 256 + threadIdx.x;
    if (blockIdx.x < 512) {
        int r = idx >> 8, k = idx & 255;
        float x = (r < 256) ? wv[r * 256 + k] : w1[(r - 256) * 256 + k];
        __nv_bfloat16 h = __float2bfloat16_rn(x);
        g_Ahi[idx] = h;
        g_Alo[idx] = __float2bfloat16_rn(x - __bfloat162float(h));
    } else {
        int i2 = idx - 512 * 256;
        int r = i2 >> 8, k = i2 & 255;
        float x = (r < 64) ? w2[r * 256 + k] : 0.f;
        __nv_bfloat16 h = __float2bfloat16_rn(x);
        g_W2hi[i2] = h;
        g_W2lo[i2] = __float2bfloat16_rn(x - __bfloat162float(h));
    }
}

// Streaming u fp32 -> bf16 hi/lo planes, same [b][c][p] layout.
__global__ __launch_bounds__(256) void convert_u(const float4* __restrict__ u)
{
    size_t i = (size_t)blockIdx.x * 256 + threadIdx.x;   // over 4.19M float4s
    float4 v = u[i];
    __nv_bfloat16 h0 = __float2bfloat16_rn(v.x), h1 = __float2bfloat16_rn(v.y);
    __nv_bfloat16 h2 = __float2bfloat16_rn(v.z), h3 = __float2bfloat16_rn(v.w);
    union { __nv_bfloat16 b[4]; uint2 q; } hh, ll;
    hh.b[0] = h0; hh.b[1] = h1; hh.b[2] = h2; hh.b[3] = h3;
    ll.b[0] = __float2bfloat16_rn(v.x - __bfloat162float(h0));
    ll.b[1] = __float2bfloat16_rn(v.y - __bfloat162float(h1));
    ll.b[2] = __float2bfloat16_rn(v.z - __bfloat162float(h2));
    ll.b[3] = __float2bfloat16_rn(v.w - __bfloat162float(h3));
    reinterpret_cast<uint2*>(g_Uhi)[i] = hh.q;
    reinterpret_cast<uint2*>(g_Ulo)[i] = ll.q;
}

// ---------------------------------------------------------------------------
// Split-bf16 mma.sync GEMM, B consumed via ldmatrix.trans from [k][n] layout.
// MODE 0: [value;h](M=512) = [wv;w1] @ u,  BM=128.
// MODE 1: flow(M=64) = w2 @ h,             BM=64.
// BN=128, BK=32, 8 warps (2x4), cp.async double-buffered k-tiles.
// ---------------------------------------------------------------------------
#define PITCHA 40      // elements; 80B rows (A, non-trans ldmatrix)
#define PITCHB 136     // elements; 272B rows (B, trans ldmatrix)

template <int MODE>
__global__ __launch_bounds__(256, 2) void gemm_kernel(const float* __restrict__ bias_a,
                                                      const float* __restrict__ bias_b)
{
    constexpr int ROWS = MODE ? 64 : 128;         // A rows per tile
    constexpr int MI   = MODE ? 2 : 4;            // 16-row m-frags per warp
    constexpr int APLANE = ROWS * PITCHA * 2;     // bytes
    constexpr int A_BUF  = 2 * APLANE;
    constexpr int A_TOT  = 2 * A_BUF;
    constexpr int BPLANE = 32 * PITCHB * 2;       // 8704
    constexpr int B_BUF  = 2 * BPLANE;
    constexpr int ACH    = ROWS * 4;              // 16B chunks per A plane

    extern __shared__ __align__(16) char smem[];
    const uint32_t uS = smem_u32(smem);
    const uint32_t uA = uS, uB = uS + A_TOT;

    const int tid = threadIdx.x, lane = tid & 31, wid = tid >> 5;
    const int wm = wid >> 2, wn = wid & 3;
    const int mtile = blockIdx.x, ntile = blockIdx.y, b = blockIdx.z;
    const int n0 = ntile * 128;

    const __nv_bfloat16* Ag[2] = {
        (MODE == 0) ? g_Ahi + (size_t)mtile * 128 * 256 : g_W2hi,
        (MODE == 0) ? g_Alo + (size_t)mtile * 128 * 256 : g_W2lo };
    const __nv_bfloat16* Bg[2] = {
        ((MODE == 0) ? g_Uhi : g_Hmhi) + (size_t)b * 256 * HW + n0,
        ((MODE == 0) ? g_Ulo : g_Hmlo) + (size_t)b * 256 * HW + n0 };

    // ---- async tile loader: k-tile kt -> buffer bf ----
    auto load_tiles = [&](int kt, int bf) {
        const int k0 = kt * 32;
        // A: 2 planes x ROWS x 4 chunks
#pragma unroll
        for (int q = tid; q < 2 * ACH; q += 256) {
            const int pl = q / ACH, qq = q % ACH;
            const int r = qq >> 2, c8 = (qq & 3) * 8;
            cpa16(uA + bf * A_BUF + pl * APLANE + (uint32_t)(r * PITCHA + c8) * 2,
                  Ag[pl] + (size_t)r * 256 + k0 + c8);
        }
        // B: 2 planes x 32 rows x 16 chunks
#pragma unroll
        for (int q = tid; q < 1024; q += 256) {
            const int pl = q >> 9, qq = q & 511;
            const int r = qq >> 4, c8 = (qq & 15) * 8;
            cpa16(uB + bf * B_BUF + pl * BPLANE + (uint32_t)(r * PITCHB + c8) * 2,
                  Bg[pl] + (size_t)(k0 + r) * HW + c8);
        }
    };

    float acc[MI][4][4];
#pragma unroll
    for (int mi = 0; mi < MI; mi++)
#pragma unroll
        for (int ni = 0; ni < 4; ni++)
#pragma unroll
            for (int e = 0; e < 4; e++) acc[mi][ni][e] = 0.f;

    load_tiles(0, 0);
    CP_COMMIT();
    CP_WAIT0();
    __syncthreads();

#pragma unroll 1
    for (int kt = 0; kt < 8; kt++) {
        const int bf = kt & 1;
        if (kt + 1 < 8) { load_tiles(kt + 1, bf ^ 1); CP_COMMIT(); }

        const uint32_t uAh = uA + bf * A_BUF, uAl = uAh + APLANE;
        const uint32_t uBh = uB + bf * B_BUF, uBl = uBh + BPLANE;
#pragma unroll
        for (int s = 0; s < 2; s++) {
            uint32_t ah[MI][4], al[MI][4];
            const uint32_t arow = (uint32_t)(wm * (ROWS / 2) + (lane & 15));
            const uint32_t aoff = 2u * (arow * PITCHA + s * 16 + (lane >> 4) * 8);
#pragma unroll
            for (int mi = 0; mi < MI; mi++) {
                const uint32_t o = aoff + 2u * (mi * 16 * PITCHA);
                ldsm_x4(ah[mi], uAh + o);
                ldsm_x4(al[mi], uAl + o);
            }
            const uint32_t bk = (uint32_t)(s * 16 + (lane & 15));
            const uint32_t brow = 2u * (bk * PITCHB);
#pragma unroll
            for (int ni = 0; ni < 4; ni++) {
                const uint32_t o = brow + 2u * (wn * 32 + ni * 8);
                uint32_t bh[2], bl[2];
                ldsm_x2t(bh, uBh + o);
                ldsm_x2t(bl, uBl + o);
#pragma unroll
                for (int mi = 0; mi < MI; mi++) {
                    mma16816(acc[mi][ni], ah[mi], bh);
                    mma16816(acc[mi][ni], ah[mi], bl);
                    mma16816(acc[mi][ni], al[mi], bh);
                }
            }
        }
        if (kt + 1 < 8) { CP_WAIT0(); }
        __syncthreads();
    }

    // ---------------- epilogue ----------------
    const int qr = lane >> 2, qc = (lane & 3) * 2;

    if (MODE == 1) {
#pragma unroll
        for (int mi = 0; mi < MI; mi++) {
            const int m0 = wm * 32 + mi * 16 + qr;            // < 64
            const float b0f = bias_a[m0], b1f = bias_a[m0 + 8];
            float* o0 = g_flow + ((size_t)b * 64 + m0) * HW + n0;
            float* o1 = o0 + (size_t)8 * HW;
#pragma unroll
            for (int ni = 0; ni < 4; ni++) {
                const int n = wn * 32 + ni * 8 + qc;
                float2 v0 = {acc[mi][ni][0] + b0f, acc[mi][ni][1] + b0f};
                float2 v1 = {acc[mi][ni][2] + b1f, acc[mi][ni][3] + b1f};
                *(float2*)&o0[n] = v0;
                *(float2*)&o1[n] = v1;
            }
        }
    } else if (mtile < 2) {
#pragma unroll
        for (int mi = 0; mi < MI; mi++) {
            const int c = mtile * 128 + wm * 64 + mi * 16 + qr;
            const float b0f = bias_b[c], b1f = bias_b[c + 8];
            float* o0 = g_value + ((size_t)b * 256 + c) * HW + n0;
            float* o1 = o0 + (size_t)8 * HW;
#pragma unroll
            for (int ni = 0; ni < 4; ni++) {
                const int n = wn * 32 + ni * 8 + qc;
                float2 v0 = {acc[mi][ni][0] + b0f, acc[mi][ni][1] + b0f};
                float2 v1 = {acc[mi][ni][2] + b1f, acc[mi][ni][3] + b1f};
                *(float2*)&o0[n] = v0;
                *(float2*)&o1[n] = v1;
            }
        }
    } else {
#pragma unroll
        for (int mi = 0; mi < MI; mi++) {
            const int c = (mtile - 2) * 128 + wm * 64 + mi * 16 + qr;
            const float b0f = bias_a[c], b1f = bias_a[c + 8];
            __nv_bfloat16* oh0 = g_Hmhi + ((size_t)b * 256 + c) * HW + n0;
            __nv_bfloat16* ol0 = g_Hmlo + ((size_t)b * 256 + c) * HW + n0;
#pragma unroll
            for (int ni = 0; ni < 4; ni++) {
                const int n = wn * 32 + ni * 8 + qc;
#pragma unroll
                for (int half = 0; half < 2; half++) {
                    const float bb = half ? b1f : b0f;
                    float x0 = fmaxf(acc[mi][ni][half * 2 + 0] + bb, 0.f);
                    float x1 = fmaxf(acc[mi][ni][half * 2 + 1] + bb, 0.f);
                    __nv_bfloat16 h0 = __float2bfloat16_rn(x0);
                    __nv_bfloat16 h1 = __float2bfloat16_rn(x1);
                    __nv_bfloat162 hh, ll;
                    hh.x = h0; hh.y = h1;
                    ll.x = __float2bfloat16_rn(x0 - __bfloat162float(h0));
                    ll.y = __float2bfloat16_rn(x1 - __bfloat162float(h1));
                    const size_t off = (size_t)(half * 8) * HW + n;
                    *(__nv_bfloat162*)&oh0[off] = hh;
                    *(__nv_bfloat162*)&ol0[off] = ll;
                }
            }
        }
    }
}

// ---------------------------------------------------------------------------
__global__ __launch_bounds__(128)
void warp_gather_kernel(float* __restrict__ out)
{
    const int x = threadIdx.x, y = blockIdx.x, bh = blockIdx.y;
    const int b = bh >> 5, head = bh & 31;

    const float* fb = g_flow + ((size_t)b * 64 + head * 2) * HW + y * WDIM + x;
    const float fx = fb[0];
    const float fy = fb[HW];

    const float gx = fmaf((float)x, 2.f / 127.f, -1.f) + fx;
    const float gy = fmaf((float)y, 2.f / 127.f, -1.f) + fy;
    const float ix = (gx + 1.f) * 63.5f;
    const float iy = (gy + 1.f) * 63.5f;

    const float x0f = floorf(ix), y0f = floorf(iy);
    const float dx = ix - x0f, dy = iy - y0f;
    const int x0 = (int)x0f, y0 = (int)y0f;
    const int x1 = x0 + 1,   y1 = y0 + 1;

    const bool vx0 = (x0 >= 0) & (x0 < WDIM);
    const bool vx1 = (x1 >= 0) & (x1 < WDIM);
    const bool vy0 = (y0 >= 0) & (y0 < WDIM);
    const bool vy1 = (y1 >= 0) & (y1 < WDIM);

    const int x0c = min(max(x0, 0), WDIM - 1);
    const int x1c = min(max(x1, 0), WDIM - 1);
    const int y0c = min(max(y0, 0), WDIM - 1);
    const int y1c = min(max(y1, 0), WDIM - 1);

    const float w00 = (1.f - dx) * (1.f - dy) * (float)(vx0 & vy0);
    const float w01 = dx * (1.f - dy)         * (float)(vx1 & vy0);
    const float w10 = (1.f - dx) * dy         * (float)(vx0 & vy1);
    const float w11 = dx * dy                 * (float)(vx1 & vy1);

    const int p00 = y0c * WDIM + x0c;
    const int p01 = y0c * WDIM + x1c;
    const int p10 = y1c * WDIM + x0c;
    const int p11 = y1c * WDIM + x1c;

    const float* vb = g_value + ((size_t)b * 256 + head * 8) * HW;
    float* ob = out + ((size_t)b * 256 + head * 8) * HW + y * WDIM + x;

#pragma unroll
    for (int ci = 0; ci < 8; ci++) {
        const float* v = vb + (size_t)ci * HW;
        ob[(size_t)ci * HW] = w00 * v[p00] + w01 * v[p01] + w10 * v[p10] + w11 * v[p11];
    }
}

// ---------------------------------------------------------------------------
extern "C" void kernel_launch(void* const* d_in, const int* in_sizes, int n_in,
                              void* d_out, int out_size)
{
    const float* u  = (const float*)d_in[0];
    const float* w1 = (const float*)d_in[1];
    const float* b1 = (const float*)d_in[2];
    const float* w2 = (const float*)d_in[3];
    const float* b2 = (const float*)d_in[4];
    const float* wv = (const float*)d_in[5];
    const float* bv = (const float*)d_in[6];
    float* out = (float*)d_out;

    constexpr int SM0 = 2 * (2 * 128 * PITCHA * 2) + 2 * (2 * 32 * PITCHB * 2);  // 75776
    constexpr int SM1 = 2 * (2 * 64  * PITCHA * 2) + 2 * (2 * 32 * PITCHB * 2);  // 55296
    static bool configured = false;
    if (!configured) {
        cudaFuncSetAttribute(gemm_kernel<0>, cudaFuncAttributeMaxDynamicSharedMemorySize, SM0);
        cudaFuncSetAttribute(gemm_kernel<1>, cudaFuncAttributeMaxDynamicSharedMemorySize, SM1);
        configured = true;
    }

    prep_weights<<<640, 256>>>(w1, wv, w2);
    convert_u<<<16384, 256>>>((const float4*)u);
    gemm_kernel<0><<<dim3(4, 128, NB), 256, SM0>>>(b1, bv);
    gemm_kernel<1><<<dim3(1, 128, NB), 256, SM1>>>(b2, nullptr);
    warp_gather_kernel<<<dim3(128, 128), 128>>>(out);
}

// round 8
// speedup vs baseline: 1.6204x; 1.0080x over previous
#include <cuda_runtime.h>
#include <cuda_bf16.h>
#include <cstdint>

#define HW   16384
#define NB   4
#define WDIM 128

// ---------------- scratch (__device__ globals) ------------------------------
__device__ __nv_bfloat16 g_Ahi[512 * 256];                 // [wv; w1] hi, [m][k]
__device__ __nv_bfloat16 g_Alo[512 * 256];
__device__ __nv_bfloat16 g_W2hi[128 * 256];                // w2 (64 rows used)
__device__ __nv_bfloat16 g_W2lo[128 * 256];
__device__ __nv_bfloat16 g_Uhi[(size_t)NB * 256 * HW];     // u hi [b][c][p]
__device__ __nv_bfloat16 g_Ulo[(size_t)NB * 256 * HW];
__device__ __nv_bfloat16 g_Hmhi[(size_t)NB * 256 * HW];    // h hi [b][c][p]
__device__ __nv_bfloat16 g_Hmlo[(size_t)NB * 256 * HW];
__device__ float g_value[(size_t)NB * 256 * HW];
__device__ float g_flow [(size_t)NB * 64 * HW];

// ---------------- helpers ---------------------------------------------------
__device__ __forceinline__ uint32_t smem_u32(const void* p) {
    uint32_t a;
    asm("{ .reg .u64 t; cvta.to.shared.u64 t, %1; cvt.u32.u64 %0, t; }" : "=r"(a) : "l"(p));
    return a;
}
__device__ __forceinline__ void ldsm_x4(uint32_t* r, uint32_t addr) {
    asm volatile("ldmatrix.sync.aligned.m8n8.x4.shared.b16 {%0,%1,%2,%3}, [%4];"
                 : "=r"(r[0]), "=r"(r[1]), "=r"(r[2]), "=r"(r[3]) : "r"(addr));
}
__device__ __forceinline__ void ldsm_x2t(uint32_t* r, uint32_t addr) {
    asm volatile("ldmatrix.sync.aligned.m8n8.x2.trans.shared.b16 {%0,%1}, [%2];"
                 : "=r"(r[0]), "=r"(r[1]) : "r"(addr));
}
__device__ __forceinline__ void mma16816(float* c, const uint32_t* a, const uint32_t* b) {
    asm volatile("mma.sync.aligned.m16n8k16.row.col.f32.bf16.bf16.f32 "
                 "{%0,%1,%2,%3}, {%4,%5,%6,%7}, {%8,%9}, {%0,%1,%2,%3};"
                 : "+f"(c[0]), "+f"(c[1]), "+f"(c[2]), "+f"(c[3])
                 : "r"(a[0]), "r"(a[1]), "r"(a[2]), "r"(a[3]), "r"(b[0]), "r"(b[1]));
}
__device__ __forceinline__ void cpa16(uint32_t dst, const void* src) {
    asm volatile("cp.async.cg.shared.global [%0], [%1], 16;" :: "r"(dst), "l"(src));
}
#define CP_COMMIT() asm volatile("cp.async.commit_group;" ::: "memory")
#define CP_WAIT0()  asm volatile("cp.async.wait_group 0;" ::: "memory")
#define CP_WAIT1()  asm volatile("cp.async.wait_group 1;" ::: "memory")

// ---------------------------------------------------------------------------
__global__ void prep_weights(const float* __restrict__ w1, const float* __restrict__ wv,
                             const float* __restrict__ w2)
{
    int idx = blockIdx.x * 256 + threadIdx.x;
    if (blockIdx.x < 512) {
        int r = idx >> 8, k = idx & 255;
        float x = (r < 256) ? wv[r * 256 + k] : w1[(r - 256) * 256 + k];
        __nv_bfloat16 h = __float2bfloat16_rn(x);
        g_Ahi[idx] = h;
        g_Alo[idx] = __float2bfloat16_rn(x - __bfloat162float(h));
    } else {
        int i2 = idx - 512 * 256;
        int r = i2 >> 8, k = i2 & 255;
        float x = (r < 64) ? w2[r * 256 + k] : 0.f;
        __nv_bfloat16 h = __float2bfloat16_rn(x);
        g_W2hi[i2] = h;
        g_W2lo[i2] = __float2bfloat16_rn(x - __bfloat162float(h));
    }
}

// Streaming u fp32 -> bf16 hi/lo planes, same [b][c][p] layout.
__global__ __launch_bounds__(256) void convert_u(const float4* __restrict__ u)
{
    size_t i = (size_t)blockIdx.x * 256 + threadIdx.x;   // over 4.19M float4s
    float4 v = u[i];
    __nv_bfloat16 h0 = __float2bfloat16_rn(v.x), h1 = __float2bfloat16_rn(v.y);
    __nv_bfloat16 h2 = __float2bfloat16_rn(v.z), h3 = __float2bfloat16_rn(v.w);
    union { __nv_bfloat16 b[4]; uint2 q; } hh, ll;
    hh.b[0] = h0; hh.b[1] = h1; hh.b[2] = h2; hh.b[3] = h3;
    ll.b[0] = __float2bfloat16_rn(v.x - __bfloat162float(h0));
    ll.b[1] = __float2bfloat16_rn(v.y - __bfloat162float(h1));
    ll.b[2] = __float2bfloat16_rn(v.z - __bfloat162float(h2));
    ll.b[3] = __float2bfloat16_rn(v.w - __bfloat162float(h3));
    reinterpret_cast<uint2*>(g_Uhi)[i] = hh.q;
    reinterpret_cast<uint2*>(g_Ulo)[i] = ll.q;
}

// ---------------------------------------------------------------------------
// Split-bf16 mma.sync GEMM, B via ldmatrix.trans from [k][n] layout.
// MODE 0: [value;h](M=512) = [wv;w1] @ u,  BM=128.
// MODE 1: flow(M=64) = w2 @ h,             BM=64.
// BN=128, BK=32, 8 warps (2x4), 3-stage cp.async ring.
// ---------------------------------------------------------------------------
#define PITCHA 40      // elements; 80B rows (A, non-trans ldmatrix)
#define PITCHB 136     // elements; 272B rows (B, trans ldmatrix)

template <int MODE>
__global__ __launch_bounds__(256, 2) void gemm_kernel(const float* __restrict__ bias_a,
                                                      const float* __restrict__ bias_b)
{
    constexpr int ROWS = MODE ? 64 : 128;         // A rows per tile
    constexpr int MI   = MODE ? 2 : 4;            // 16-row m-frags per warp
    constexpr int APLANE = ROWS * PITCHA * 2;     // bytes
    constexpr int A_BUF  = 2 * APLANE;
    constexpr int BPLANE = 32 * PITCHB * 2;       // 8704
    constexpr int B_BUF  = 2 * BPLANE;
    constexpr int STAGE  = A_BUF + B_BUF;
    constexpr int ACH    = ROWS * 4;              // 16B chunks per A plane

    extern __shared__ __align__(16) char smem[];
    const uint32_t uS = smem_u32(smem);

    const int tid = threadIdx.x, lane = tid & 31, wid = tid >> 5;
    const int wm = wid >> 2, wn = wid & 3;
    const int mtile = blockIdx.x, ntile = blockIdx.y, b = blockIdx.z;
    const int n0 = ntile * 128;

    const __nv_bfloat16* Ag[2] = {
        (MODE == 0) ? g_Ahi + (size_t)mtile * 128 * 256 : g_W2hi,
        (MODE == 0) ? g_Alo + (size_t)mtile * 128 * 256 : g_W2lo };
    const __nv_bfloat16* Bg[2] = {
        ((MODE == 0) ? g_Uhi : g_Hmhi) + (size_t)b * 256 * HW + n0,
        ((MODE == 0) ? g_Ulo : g_Hmlo) + (size_t)b * 256 * HW + n0 };

    // ---- async tile loader: k-tile kt -> ring stage st ----
    auto load_tiles = [&](int kt, int st) {
        const int k0 = kt * 32;
        const uint32_t base = uS + (uint32_t)st * STAGE;
#pragma unroll
        for (int q = tid; q < 2 * ACH; q += 256) {
            const int pl = q / ACH, qq = q % ACH;
            const int r = qq >> 2, c8 = (qq & 3) * 8;
            cpa16(base + pl * APLANE + (uint32_t)(r * PITCHA + c8) * 2,
                  Ag[pl] + (size_t)r * 256 + k0 + c8);
        }
#pragma unroll
        for (int q = tid; q < 1024; q += 256) {
            const int pl = q >> 9, qq = q & 511;
            const int r = qq >> 4, c8 = (qq & 15) * 8;
            cpa16(base + A_BUF + pl * BPLANE + (uint32_t)(r * PITCHB + c8) * 2,
                  Bg[pl] + (size_t)(k0 + r) * HW + c8);
        }
    };

    float acc[MI][4][4];
#pragma unroll
    for (int mi = 0; mi < MI; mi++)
#pragma unroll
        for (int ni = 0; ni < 4; ni++)
#pragma unroll
            for (int e = 0; e < 4; e++) acc[mi][ni][e] = 0.f;

    load_tiles(0, 0); CP_COMMIT();
    load_tiles(1, 1); CP_COMMIT();

#pragma unroll 1
    for (int kt = 0; kt < 8; kt++) {
        const int st = kt % 3;
        if (kt < 7) { CP_WAIT1(); } else { CP_WAIT0(); }
        __syncthreads();

        const uint32_t uAh = uS + (uint32_t)st * STAGE, uAl = uAh + APLANE;
        const uint32_t uBh = uAh + A_BUF,               uBl = uBh + BPLANE;
#pragma unroll
        for (int s = 0; s < 2; s++) {
            uint32_t ah[MI][4], al[MI][4];
            const uint32_t arow = (uint32_t)(wm * (ROWS / 2) + (lane & 15));
            const uint32_t aoff = 2u * (arow * PITCHA + s * 16 + (lane >> 4) * 8);
#pragma unroll
            for (int mi = 0; mi < MI; mi++) {
                const uint32_t o = aoff + 2u * (mi * 16 * PITCHA);
                ldsm_x4(ah[mi], uAh + o);
                ldsm_x4(al[mi], uAl + o);
            }
            const uint32_t bk = (uint32_t)(s * 16 + (lane & 15));
            const uint32_t brow = 2u * (bk * PITCHB);
#pragma unroll
            for (int ni = 0; ni < 4; ni++) {
                const uint32_t o = brow + 2u * (wn * 32 + ni * 8);
                uint32_t bh[2], bl[2];
                ldsm_x2t(bh, uBh + o);
                ldsm_x2t(bl, uBl + o);
#pragma unroll
                for (int mi = 0; mi < MI; mi++) {
                    mma16816(acc[mi][ni], ah[mi], bh);
                    mma16816(acc[mi][ni], ah[mi], bl);
                    mma16816(acc[mi][ni], al[mi], bh);
                }
            }
        }
        // stage (kt+2)%3 was last read at iteration kt-1; safe after the sync above.
        if (kt + 2 < 8) {
            __syncthreads();           // ensure all warps done with stage (kt+2)%3 == (kt-1)%3
            load_tiles(kt + 2, (kt + 2) % 3);
            CP_COMMIT();
        }
    }

    // ---------------- epilogue ----------------
    const int qr = lane >> 2, qc = (lane & 3) * 2;

    if (MODE == 1) {
#pragma unroll
        for (int mi = 0; mi < MI; mi++) {
            const int m0 = wm * 32 + mi * 16 + qr;            // < 64
            const float b0f = bias_a[m0], b1f = bias_a[m0 + 8];
            float* o0 = g_flow + ((size_t)b * 64 + m0) * HW + n0;
            float* o1 = o0 + (size_t)8 * HW;
#pragma unroll
            for (int ni = 0; ni < 4; ni++) {
                const int n = wn * 32 + ni * 8 + qc;
                float2 v0 = {acc[mi][ni][0] + b0f, acc[mi][ni][1] + b0f};
                float2 v1 = {acc[mi][ni][2] + b1f, acc[mi][ni][3] + b1f};
                *(float2*)&o0[n] = v0;
                *(float2*)&o1[n] = v1;
            }
        }
    } else if (mtile < 2) {
#pragma unroll
        for (int mi = 0; mi < MI; mi++) {
            const int c = mtile * 128 + wm * 64 + mi * 16 + qr;
            const float b0f = bias_b[c], b1f = bias_b[c + 8];
            float* o0 = g_value + ((size_t)b * 256 + c) * HW + n0;
            float* o1 = o0 + (size_t)8 * HW;
#pragma unroll
            for (int ni = 0; ni < 4; ni++) {
                const int n = wn * 32 + ni * 8 + qc;
                float2 v0 = {acc[mi][ni][0] + b0f, acc[mi][ni][1] + b0f};
                float2 v1 = {acc[mi][ni][2] + b1f, acc[mi][ni][3] + b1f};
                *(float2*)&o0[n] = v0;
                *(float2*)&o1[n] = v1;
            }
        }
    } else {
#pragma unroll
        for (int mi = 0; mi < MI; mi++) {
            const int c = (mtile - 2) * 128 + wm * 64 + mi * 16 + qr;
            const float b0f = bias_a[c], b1f = bias_a[c + 8];
            __nv_bfloat16* oh0 = g_Hmhi + ((size_t)b * 256 + c) * HW + n0;
            __nv_bfloat16* ol0 = g_Hmlo + ((size_t)b * 256 + c) * HW + n0;
#pragma unroll
            for (int ni = 0; ni < 4; ni++) {
                const int n = wn * 32 + ni * 8 + qc;
#pragma unroll
                for (int half = 0; half < 2; half++) {
                    const float bb = half ? b1f : b0f;
                    float x0 = fmaxf(acc[mi][ni][half * 2 + 0] + bb, 0.f);
                    float x1 = fmaxf(acc[mi][ni][half * 2 + 1] + bb, 0.f);
                    __nv_bfloat16 h0 = __float2bfloat16_rn(x0);
                    __nv_bfloat16 h1 = __float2bfloat16_rn(x1);
                    __nv_bfloat162 hh, ll;
                    hh.x = h0; hh.y = h1;
                    ll.x = __float2bfloat16_rn(x0 - __bfloat162float(h0));
                    ll.y = __float2bfloat16_rn(x1 - __bfloat162float(h1));
                    const size_t off = (size_t)(half * 8) * HW + n;
                    *(__nv_bfloat162*)&oh0[off] = hh;
                    *(__nv_bfloat162*)&ol0[off] = ll;
                }
            }
        }
    }
}

// ---------------------------------------------------------------------------
__global__ __launch_bounds__(128)
void warp_gather_kernel(float* __restrict__ out)
{
    const int x = threadIdx.x, y = blockIdx.x, bh = blockIdx.y;
    const int b = bh >> 5, head = bh & 31;

    const float* fb = g_flow + ((size_t)b * 64 + head * 2) * HW + y * WDIM + x;
    const float fx = fb[0];
    const float fy = fb[HW];

    const float gx = fmaf((float)x, 2.f / 127.f, -1.f) + fx;
    const float gy = fmaf((float)y, 2.f / 127.f, -1.f) + fy;
    const float ix = (gx + 1.f) * 63.5f;
    const float iy = (gy + 1.f) * 63.5f;

    const float x0f = floorf(ix), y0f = floorf(iy);
    const float dx = ix - x0f, dy = iy - y0f;
    const int x0 = (int)x0f, y0 = (int)y0f;
    const int x1 = x0 + 1,   y1 = y0 + 1;

    const bool vx0 = (x0 >= 0) & (x0 < WDIM);
    const bool vx1 = (x1 >= 0) & (x1 < WDIM);
    const bool vy0 = (y0 >= 0) & (y0 < WDIM);
    const bool vy1 = (y1 >= 0) & (y1 < WDIM);

    const int x0c = min(max(x0, 0), WDIM - 1);
    const int x1c = min(max(x1, 0), WDIM - 1);
    const int y0c = min(max(y0, 0), WDIM - 1);
    const int y1c = min(max(y1, 0), WDIM - 1);

    const float w00 = (1.f - dx) * (1.f - dy) * (float)(vx0 & vy0);
    const float w01 = dx * (1.f - dy)         * (float)(vx1 & vy0);
    const float w10 = (1.f - dx) * dy         * (float)(vx0 & vy1);
    const float w11 = dx * dy                 * (float)(vx1 & vy1);

    const int p00 = y0c * WDIM + x0c;
    const int p01 = y0c * WDIM + x1c;
    const int p10 = y1c * WDIM + x0c;
    const int p11 = y1c * WDIM + x1c;

    const float* vb = g_value + ((size_t)b * 256 + head * 8) * HW;
    float* ob = out + ((size_t)b * 256 + head * 8) * HW + y * WDIM + x;

#pragma unroll
    for (int ci = 0; ci < 8; ci++) {
        const float* v = vb + (size_t)ci * HW;
        ob[(size_t)ci * HW] = w00 * v[p00] + w01 * v[p01] + w10 * v[p10] + w11 * v[p11];
    }
}

// ---------------------------------------------------------------------------
extern "C" void kernel_launch(void* const* d_in, const int* in_sizes, int n_in,
                              void* d_out, int out_size)
{
    const float* u  = (const float*)d_in[0];
    const float* w1 = (const float*)d_in[1];
    const float* b1 = (const float*)d_in[2];
    const float* w2 = (const float*)d_in[3];
    const float* b2 = (const float*)d_in[4];
    const float* wv = (const float*)d_in[5];
    const float* bv = (const float*)d_in[6];
    float* out = (float*)d_out;

    constexpr int SM0 = 3 * (2 * 2 * 128 * PITCHA + 2 * 2 * 32 * PITCHB);   // 113664
    constexpr int SM1 = 3 * (2 * 2 * 64  * PITCHA + 2 * 2 * 32 * PITCHB);   // 82944
    static bool configured = false;
    if (!configured) {
        cudaFuncSetAttribute(gemm_kernel<0>, cudaFuncAttributeMaxDynamicSharedMemorySize, SM0);
        cudaFuncSetAttribute(gemm_kernel<1>, cudaFuncAttributeMaxDynamicSharedMemorySize, SM1);
        configured = true;
    }

    prep_weights<<<640, 256>>>(w1, wv, w2);
    convert_u<<<16384, 256>>>((const float4*)u);
    gemm_kernel<0><<<dim3(4, 128, NB), 256, SM0>>>(b1, bv);
    gemm_kernel<1><<<dim3(1, 128, NB), 256, SM1>>>(b2, nullptr);
    warp_gather_kernel<<<dim3(128, 128), 128>>>(out);
}

// round 9
// speedup vs baseline: 1.7371x; 1.0720x over previous
#include <cuda_runtime.h>
#include <cuda_fp16.h>
#include <cstdint>

#define HW   16384
#define NB   4
#define WDIM 128

// ---------------- scratch (__device__ globals) ------------------------------
__device__ __half g_Ahi[512 * 256];                 // [wv; w1] hi, [m][k]
__device__ __half g_Alo[512 * 256];
__device__ __half g_W2hi[128 * 256];                // w2 (64 rows used)
__device__ __half g_W2lo[128 * 256];
__device__ __half g_Uhi[(size_t)NB * 256 * HW];     // u hi [b][c][p]
__device__ __half g_Ulo[(size_t)NB * 256 * HW];
__device__ __half g_Hmhi[(size_t)NB * 256 * HW];    // h hi [b][c][p]
__device__ __half g_Hmlo[(size_t)NB * 256 * HW];
__device__ float g_value[(size_t)NB * 256 * HW];
__device__ float g_flow [(size_t)NB * 64 * HW];

// ---------------- helpers ---------------------------------------------------
__device__ __forceinline__ uint32_t smem_u32(const void* p) {
    uint32_t a;
    asm("{ .reg .u64 t; cvta.to.shared.u64 t, %1; cvt.u32.u64 %0, t; }" : "=r"(a) : "l"(p));
    return a;
}
__device__ __forceinline__ void ldsm_x4(uint32_t* r, uint32_t addr) {
    asm volatile("ldmatrix.sync.aligned.m8n8.x4.shared.b16 {%0,%1,%2,%3}, [%4];"
                 : "=r"(r[0]), "=r"(r[1]), "=r"(r[2]), "=r"(r[3]) : "r"(addr));
}
__device__ __forceinline__ void ldsm_x2t(uint32_t* r, uint32_t addr) {
    asm volatile("ldmatrix.sync.aligned.m8n8.x2.trans.shared.b16 {%0,%1}, [%2];"
                 : "=r"(r[0]), "=r"(r[1]) : "r"(addr));
}
__device__ __forceinline__ void mma16816(float* c, const uint32_t* a, const uint32_t* b) {
    asm volatile("mma.sync.aligned.m16n8k16.row.col.f32.f16.f16.f32 "
                 "{%0,%1,%2,%3}, {%4,%5,%6,%7}, {%8,%9}, {%0,%1,%2,%3};"
                 : "+f"(c[0]), "+f"(c[1]), "+f"(c[2]), "+f"(c[3])
                 : "r"(a[0]), "r"(a[1]), "r"(a[2]), "r"(a[3]), "r"(b[0]), "r"(b[1]));
}
__device__ __forceinline__ void cpa16(uint32_t dst, const void* src) {
    asm volatile("cp.async.cg.shared.global [%0], [%1], 16;" :: "r"(dst), "l"(src));
}
#define CP_COMMIT() asm volatile("cp.async.commit_group;" ::: "memory")
#define CP_WAIT0()  asm volatile("cp.async.wait_group 0;" ::: "memory")
#define CP_WAIT1()  asm volatile("cp.async.wait_group 1;" ::: "memory")

// ---------------------------------------------------------------------------
__global__ void prep_weights(const float* __restrict__ w1, const float* __restrict__ wv,
                             const float* __restrict__ w2)
{
    int idx = blockIdx.x * 256 + threadIdx.x;
    if (blockIdx.x < 512) {
        int r = idx >> 8, k = idx & 255;
        float x = (r < 256) ? wv[r * 256 + k] : w1[(r - 256) * 256 + k];
        __half h = __float2half_rn(x);
        g_Ahi[idx] = h;
        g_Alo[idx] = __float2half_rn(x - __half2float(h));
    } else {
        int i2 = idx - 512 * 256;
        int r = i2 >> 8, k = i2 & 255;
        float x = (r < 64) ? w2[r * 256 + k] : 0.f;
        __half h = __float2half_rn(x);
        g_W2hi[i2] = h;
        g_W2lo[i2] = __float2half_rn(x - __half2float(h));
    }
}

// Streaming u fp32 -> fp16 hi/lo planes, same [b][c][p] layout.
__global__ __launch_bounds__(256) void convert_u(const float4* __restrict__ u)
{
    size_t i = (size_t)blockIdx.x * 256 + threadIdx.x;   // over 4.19M float4s
    float4 v = u[i];
    __half h0 = __float2half_rn(v.x), h1 = __float2half_rn(v.y);
    __half h2 = __float2half_rn(v.z), h3 = __float2half_rn(v.w);
    union { __half b[4]; uint2 q; } hh, ll;
    hh.b[0] = h0; hh.b[1] = h1; hh.b[2] = h2; hh.b[3] = h3;
    ll.b[0] = __float2half_rn(v.x - __half2float(h0));
    ll.b[1] = __float2half_rn(v.y - __half2float(h1));
    ll.b[2] = __float2half_rn(v.z - __half2float(h2));
    ll.b[3] = __float2half_rn(v.w - __half2float(h3));
    reinterpret_cast<uint2*>(g_Uhi)[i] = hh.q;
    reinterpret_cast<uint2*>(g_Ulo)[i] = ll.q;
}

// ---------------------------------------------------------------------------
// Split-fp16 mma.sync GEMM, B via ldmatrix.trans from [k][n] layout.
// MODE 0: [value;h](M=512) = [wv;w1] @ u,  BM=128.
//         mtile<2 (value): 2-term  wvhi*uhi + wvlo*uhi   (no B-lo plane)
//         mtile>=2 (h):    3-term  ahi*bhi + ahi*blo + alo*bhi
// MODE 1: flow(M=64) = w2 @ h,  BM=64, 3-term.
// BN=128, BK=32, 8 warps (2x4), 3-stage cp.async ring, 1 sync/iter.
// ---------------------------------------------------------------------------
#define PITCHA 40      // elements; 80B rows (A, non-trans ldmatrix)
#define PITCHB 136     // elements; 272B rows (B, trans ldmatrix)

template <int MODE>
__global__ __launch_bounds__(256, 2) void gemm_kernel(const float* __restrict__ bias_a,
                                                      const float* __restrict__ bias_b)
{
    constexpr int ROWS = MODE ? 64 : 128;         // A rows per tile
    constexpr int MI   = MODE ? 2 : 4;            // 16-row m-frags per warp
    constexpr int APLANE = ROWS * PITCHA * 2;     // bytes
    constexpr int A_BUF  = 2 * APLANE;
    constexpr int BPLANE = 32 * PITCHB * 2;       // 8704
    constexpr int B_BUF  = 2 * BPLANE;
    constexpr int STAGE  = A_BUF + B_BUF;
    constexpr int ACH    = ROWS * 4;              // 16B chunks per A plane

    extern __shared__ __align__(16) char smem[];
    const uint32_t uS = smem_u32(smem);

    const int tid = threadIdx.x, lane = tid & 31, wid = tid >> 5;
    const int wm = wid >> 2, wn = wid & 3;
    const int mtile = blockIdx.x, ntile = blockIdx.y, b = blockIdx.z;
    const int n0 = ntile * 128;
    const bool three_term = (MODE == 1) || (mtile >= 2);

    const __half* Ag[2] = {
        (MODE == 0) ? g_Ahi + (size_t)mtile * 128 * 256 : g_W2hi,
        (MODE == 0) ? g_Alo + (size_t)mtile * 128 * 256 : g_W2lo };
    const __half* Bg[2] = {
        ((MODE == 0) ? g_Uhi : g_Hmhi) + (size_t)b * 256 * HW + n0,
        ((MODE == 0) ? g_Ulo : g_Hmlo) + (size_t)b * 256 * HW + n0 };

    // ---- async tile loader: k-tile kt -> ring stage st ----
    auto load_tiles = [&](int kt, int st) {
        const int k0 = kt * 32;
        const uint32_t base = uS + (uint32_t)st * STAGE;
#pragma unroll
        for (int q = tid; q < 2 * ACH; q += 256) {
            const int pl = q / ACH, qq = q % ACH;
            const int r = qq >> 2, c8 = (qq & 3) * 8;
            cpa16(base + pl * APLANE + (uint32_t)(r * PITCHA + c8) * 2,
                  Ag[pl] + (size_t)r * 256 + k0 + c8);
        }
        const int nb = three_term ? 1024 : 512;   // 2 planes or 1
#pragma unroll
        for (int q = tid; q < nb; q += 256) {
            const int pl = q >> 9, qq = q & 511;
            const int r = qq >> 4, c8 = (qq & 15) * 8;
            cpa16(base + A_BUF + pl * BPLANE + (uint32_t)(r * PITCHB + c8) * 2,
                  Bg[pl] + (size_t)(k0 + r) * HW + c8);
        }
    };

    float acc[MI][4][4];
#pragma unroll
    for (int mi = 0; mi < MI; mi++)
#pragma unroll
        for (int ni = 0; ni < 4; ni++)
#pragma unroll
            for (int e = 0; e < 4; e++) acc[mi][ni][e] = 0.f;

    load_tiles(0, 0); CP_COMMIT();
    load_tiles(1, 1); CP_COMMIT();

#pragma unroll 1
    for (int kt = 0; kt < 8; kt++) {
        const int st = kt % 3;
        if (kt < 7) { CP_WAIT1(); } else { CP_WAIT0(); }
        __syncthreads();

        const uint32_t uAh = uS + (uint32_t)st * STAGE, uAl = uAh + APLANE;
        const uint32_t uBh = uAh + A_BUF,               uBl = uBh + BPLANE;
#pragma unroll
        for (int s = 0; s < 2; s++) {
            uint32_t ah[MI][4], al[MI][4];
            const uint32_t arow = (uint32_t)(wm * (ROWS / 2) + (lane & 15));
            const uint32_t aoff = 2u * (arow * PITCHA + s * 16 + (lane >> 4) * 8);
#pragma unroll
            for (int mi = 0; mi < MI; mi++) {
                const uint32_t o = aoff + 2u * (mi * 16 * PITCHA);
                ldsm_x4(ah[mi], uAh + o);
                ldsm_x4(al[mi], uAl + o);
            }
            const uint32_t bk = (uint32_t)(s * 16 + (lane & 15));
            const uint32_t brow = 2u * (bk * PITCHB);
            if (three_term) {
#pragma unroll
                for (int ni = 0; ni < 4; ni++) {
                    const uint32_t o = brow + 2u * (wn * 32 + ni * 8);
                    uint32_t bh[2], bl[2];
                    ldsm_x2t(bh, uBh + o);
                    ldsm_x2t(bl, uBl + o);
#pragma unroll
                    for (int mi = 0; mi < MI; mi++) {
                        mma16816(acc[mi][ni], ah[mi], bh);
                        mma16816(acc[mi][ni], ah[mi], bl);
                        mma16816(acc[mi][ni], al[mi], bh);
                    }
                }
            } else {
#pragma unroll
                for (int ni = 0; ni < 4; ni++) {
                    const uint32_t o = brow + 2u * (wn * 32 + ni * 8);
                    uint32_t bh[2];
                    ldsm_x2t(bh, uBh + o);
#pragma unroll
                    for (int mi = 0; mi < MI; mi++) {
                        mma16816(acc[mi][ni], ah[mi], bh);
                        mma16816(acc[mi][ni], al[mi], bh);
                    }
                }
            }
        }
        // stage (kt+2)%3 == (kt-1)%3: all warps passed this iter's sync,
        // so their reads of that stage (iter kt-1) are complete.
        if (kt + 2 < 8) { load_tiles(kt + 2, (kt + 2) % 3); CP_COMMIT(); }
    }

    // ---------------- epilogue ----------------
    const int qr = lane >> 2, qc = (lane & 3) * 2;

    if (MODE == 1) {
#pragma unroll
        for (int mi = 0; mi < MI; mi++) {
            const int m0 = wm * 32 + mi * 16 + qr;            // < 64
            const float b0f = bias_a[m0], b1f = bias_a[m0 + 8];
            float* o0 = g_flow + ((size_t)b * 64 + m0) * HW + n0;
            float* o1 = o0 + (size_t)8 * HW;
#pragma unroll
            for (int ni = 0; ni < 4; ni++) {
                const int n = wn * 32 + ni * 8 + qc;
                float2 v0 = {acc[mi][ni][0] + b0f, acc[mi][ni][1] + b0f};
                float2 v1 = {acc[mi][ni][2] + b1f, acc[mi][ni][3] + b1f};
                *(float2*)&o0[n] = v0;
                *(float2*)&o1[n] = v1;
            }
        }
    } else if (mtile < 2) {
#pragma unroll
        for (int mi = 0; mi < MI; mi++) {
            const int c = mtile * 128 + wm * 64 + mi * 16 + qr;
            const float b0f = bias_b[c], b1f = bias_b[c + 8];
            float* o0 = g_value + ((size_t)b * 256 + c) * HW + n0;
            float* o1 = o0 + (size_t)8 * HW;
#pragma unroll
            for (int ni = 0; ni < 4; ni++) {
                const int n = wn * 32 + ni * 8 + qc;
                float2 v0 = {acc[mi][ni][0] + b0f, acc[mi][ni][1] + b0f};
                float2 v1 = {acc[mi][ni][2] + b1f, acc[mi][ni][3] + b1f};
                *(float2*)&o0[n] = v0;
                *(float2*)&o1[n] = v1;
            }
        }
    } else {
#pragma unroll
        for (int mi = 0; mi < MI; mi++) {
            const int c = (mtile - 2) * 128 + wm * 64 + mi * 16 + qr;
            const float b0f = bias_a[c], b1f = bias_a[c + 8];
            __half* oh0 = g_Hmhi + ((size_t)b * 256 + c) * HW + n0;
            __half* ol0 = g_Hmlo + ((size_t)b * 256 + c) * HW + n0;
#pragma unroll
            for (int ni = 0; ni < 4; ni++) {
                const int n = wn * 32 + ni * 8 + qc;
#pragma unroll
                for (int half2i = 0; half2i < 2; half2i++) {
                    const float bb = half2i ? b1f : b0f;
                    float x0 = fmaxf(acc[mi][ni][half2i * 2 + 0] + bb, 0.f);
                    float x1 = fmaxf(acc[mi][ni][half2i * 2 + 1] + bb, 0.f);
                    __half h0 = __float2half_rn(x0);
                    __half h1 = __float2half_rn(x1);
                    union { __half v[2]; uint32_t q; } hh, ll;
                    hh.v[0] = h0; hh.v[1] = h1;
                    ll.v[0] = __float2half_rn(x0 - __half2float(h0));
                    ll.v[1] = __float2half_rn(x1 - __half2float(h1));
                    const size_t off = (size_t)(half2i * 8) * HW + n;
                    *reinterpret_cast<uint32_t*>(oh0 + off) = hh.q;
                    *reinterpret_cast<uint32_t*>(ol0 + off) = ll.q;
                }
            }
        }
    }
}

// ---------------------------------------------------------------------------
__global__ __launch_bounds__(128)
void warp_gather_kernel(float* __restrict__ out)
{
    const int x = threadIdx.x, y = blockIdx.x, bh = blockIdx.y;
    const int b = bh >> 5, head = bh & 31;

    const float* fb = g_flow + ((size_t)b * 64 + head * 2) * HW + y * WDIM + x;
    const float fx = fb[0];
    const float fy = fb[HW];

    const float gx = fmaf((float)x, 2.f / 127.f, -1.f) + fx;
    const float gy = fmaf((float)y, 2.f / 127.f, -1.f) + fy;
    const float ix = (gx + 1.f) * 63.5f;
    const float iy = (gy + 1.f) * 63.5f;

    const float x0f = floorf(ix), y0f = floorf(iy);
    const float dx = ix - x0f, dy = iy - y0f;
    const int x0 = (int)x0f, y0 = (int)y0f;
    const int x1 = x0 + 1,   y1 = y0 + 1;

    const bool vx0 = (x0 >= 0) & (x0 < WDIM);
    const bool vx1 = (x1 >= 0) & (x1 < WDIM);
    const bool vy0 = (y0 >= 0) & (y0 < WDIM);
    const bool vy1 = (y1 >= 0) & (y1 < WDIM);

    const int x0c = min(max(x0, 0), WDIM - 1);
    const int x1c = min(max(x1, 0), WDIM - 1);
    const int y0c = min(max(y0, 0), WDIM - 1);
    const int y1c = min(max(y1, 0), WDIM - 1);

    const float w00 = (1.f - dx) * (1.f - dy) * (float)(vx0 & vy0);
    const float w01 = dx * (1.f - dy)         * (float)(vx1 & vy0);
    const float w10 = (1.f - dx) * dy         * (float)(vx0 & vy1);
    const float w11 = dx * dy                 * (float)(vx1 & vy1);

    const int p00 = y0c * WDIM + x0c;
    const int p01 = y0c * WDIM + x1c;
    const int p10 = y1c * WDIM + x0c;
    const int p11 = y1c * WDIM + x1c;

    const float* vb = g_value + ((size_t)b * 256 + head * 8) * HW;
    float* ob = out + ((size_t)b * 256 + head * 8) * HW + y * WDIM + x;

#pragma unroll
    for (int ci = 0; ci < 8; ci++) {
        const float* v = vb + (size_t)ci * HW;
        ob[(size_t)ci * HW] = w00 * v[p00] + w01 * v[p01] + w10 * v[p10] + w11 * v[p11];
    }
}

// ---------------------------------------------------------------------------
extern "C" void kernel_launch(void* const* d_in, const int* in_sizes, int n_in,
                              void* d_out, int out_size)
{
    const float* u  = (const float*)d_in[0];
    const float* w1 = (const float*)d_in[1];
    const float* b1 = (const float*)d_in[2];
    const float* w2 = (const float*)d_in[3];
    const float* b2 = (const float*)d_in[4];
    const float* wv = (const float*)d_in[5];
    const float* bv = (const float*)d_in[6];
    float* out = (float*)d_out;

    constexpr int SM0 = 3 * (2 * 2 * 128 * PITCHA + 2 * 2 * 32 * PITCHB);   // 113664
    constexpr int SM1 = 3 * (2 * 2 * 64  * PITCHA + 2 * 2 * 32 * PITCHB);   // 82944
    static bool configured = false;
    if (!configured) {
        cudaFuncSetAttribute(gemm_kernel<0>, cudaFuncAttributeMaxDynamicSharedMemorySize, SM0);
        cudaFuncSetAttribute(gemm_kernel<1>, cudaFuncAttributeMaxDynamicSharedMemorySize, SM1);
        configured = true;
    }

    prep_weights<<<640, 256>>>(w1, wv, w2);
    convert_u<<<16384, 256>>>((const float4*)u);
    gemm_kernel<0><<<dim3(4, 128, NB), 256, SM0>>>(b1, bv);
    gemm_kernel<1><<<dim3(1, 128, NB), 256, SM1>>>(b2, nullptr);
    warp_gather_kernel<<<dim3(128, 128), 128>>>(out);
}

// round 10
// speedup vs baseline: 1.8201x; 1.0478x over previous
#include <cuda_runtime.h>
#include <cuda_fp16.h>
#include <cstdint>

#define HW   16384
#define NB   4
#define WDIM 128

// ---------------- scratch (__device__ globals) ------------------------------
__device__ __half g_Ahi[512 * 256];                 // rows 0-255 wv, 256-511 w1
__device__ __half g_Alo[512 * 256];
__device__ __half g_W2hi[128 * 256];                // w2 (64 rows used)
__device__ __half g_W2lo[128 * 256];
__device__ __half g_Uhi[(size_t)NB * 256 * HW];     // u hi [b][c][p]
__device__ __half g_Ulo[(size_t)NB * 256 * HW];
__device__ __half g_Hmhi[(size_t)NB * 256 * HW];    // h hi [b][c][p]
__device__ __half g_Hmlo[(size_t)NB * 256 * HW];
__device__ float g_value[(size_t)NB * 256 * HW];
__device__ float g_flow [(size_t)NB * 64 * HW];

// ---------------- helpers ---------------------------------------------------
__device__ __forceinline__ uint32_t smem_u32(const void* p) {
    uint32_t a;
    asm("{ .reg .u64 t; cvta.to.shared.u64 t, %1; cvt.u32.u64 %0, t; }" : "=r"(a) : "l"(p));
    return a;
}
__device__ __forceinline__ void ldsm_x4(uint32_t* r, uint32_t addr) {
    asm volatile("ldmatrix.sync.aligned.m8n8.x4.shared.b16 {%0,%1,%2,%3}, [%4];"
                 : "=r"(r[0]), "=r"(r[1]), "=r"(r[2]), "=r"(r[3]) : "r"(addr));
}
__device__ __forceinline__ void ldsm_x2t(uint32_t* r, uint32_t addr) {
    asm volatile("ldmatrix.sync.aligned.m8n8.x2.trans.shared.b16 {%0,%1}, [%2];"
                 : "=r"(r[0]), "=r"(r[1]) : "r"(addr));
}
__device__ __forceinline__ void mma16816(float* c, const uint32_t* a, const uint32_t* b) {
    asm volatile("mma.sync.aligned.m16n8k16.row.col.f32.f16.f16.f32 "
                 "{%0,%1,%2,%3}, {%4,%5,%6,%7}, {%8,%9}, {%0,%1,%2,%3};"
                 : "+f"(c[0]), "+f"(c[1]), "+f"(c[2]), "+f"(c[3])
                 : "r"(a[0]), "r"(a[1]), "r"(a[2]), "r"(a[3]), "r"(b[0]), "r"(b[1]));
}
__device__ __forceinline__ void cpa16(uint32_t dst, const void* src) {
    asm volatile("cp.async.cg.shared.global [%0], [%1], 16;" :: "r"(dst), "l"(src));
}
#define CP_COMMIT() asm volatile("cp.async.commit_group;" ::: "memory")
#define CP_WAIT0()  asm volatile("cp.async.wait_group 0;" ::: "memory")
#define CP_WAIT1()  asm volatile("cp.async.wait_group 1;" ::: "memory")

// ---------------------------------------------------------------------------
__global__ void prep_weights(const float* __restrict__ w1, const float* __restrict__ wv,
                             const float* __restrict__ w2)
{
    int idx = blockIdx.x * 256 + threadIdx.x;
    if (blockIdx.x < 512) {
        int r = idx >> 8, k = idx & 255;
        float x = (r < 256) ? wv[r * 256 + k] : w1[(r - 256) * 256 + k];
        __half h = __float2half_rn(x);
        g_Ahi[idx] = h;
        g_Alo[idx] = __float2half_rn(x - __half2float(h));
    } else {
        int i2 = idx - 512 * 256;
        int r = i2 >> 8, k = i2 & 255;
        float x = (r < 64) ? w2[r * 256 + k] : 0.f;
        __half h = __float2half_rn(x);
        g_W2hi[i2] = h;
        g_W2lo[i2] = __float2half_rn(x - __half2float(h));
    }
}

// Streaming u fp32 -> fp16 hi/lo planes; 2 float4 per thread.
__global__ __launch_bounds__(256) void convert_u(const float4* __restrict__ u)
{
    size_t base = (size_t)blockIdx.x * 512 + threadIdx.x;
#pragma unroll
    for (int j = 0; j < 2; j++) {
        size_t i = base + j * 256;
        float4 v = u[i];
        __half h0 = __float2half_rn(v.x), h1 = __float2half_rn(v.y);
        __half h2 = __float2half_rn(v.z), h3 = __float2half_rn(v.w);
        union { __half b[4]; uint2 q; } hh, ll;
        hh.b[0] = h0; hh.b[1] = h1; hh.b[2] = h2; hh.b[3] = h3;
        ll.b[0] = __float2half_rn(v.x - __half2float(h0));
        ll.b[1] = __float2half_rn(v.y - __half2float(h1));
        ll.b[2] = __float2half_rn(v.z - __half2float(h2));
        ll.b[3] = __float2half_rn(v.w - __half2float(h3));
        reinterpret_cast<uint2*>(g_Uhi)[i] = hh.q;
        reinterpret_cast<uint2*>(g_Ulo)[i] = ll.q;
    }
}

// ---------------------------------------------------------------------------
// Split-fp16 mma.sync GEMM, B via ldmatrix.trans from [k][n] layout.
// MODE 0: h = relu(w1@u+b1)   BM=128, 3-term, mtile in {0,1}
// MODE 1: flow = w2@h+b2      BM=64,  3-term
// MODE 2: value = wv@u+bv     BM=128, 2-term (no B-lo plane)
// BN=128, BK=32, 8 warps (2x4), 3-stage cp.async ring.
// ---------------------------------------------------------------------------
#define PITCHA 40      // elements; 80B rows (A, non-trans ldmatrix)
#define PITCHB 136     // elements; 272B rows (B, trans ldmatrix)

template <int MODE>
__global__ __launch_bounds__(256, 2) void gemm_kernel(const float* __restrict__ bias)
{
    constexpr bool THREE = (MODE != 2);
    constexpr int ROWS = (MODE == 1) ? 64 : 128;
    constexpr int MI   = (MODE == 1) ? 2 : 4;
    constexpr int APLANE = ROWS * PITCHA * 2;
    constexpr int A_BUF  = 2 * APLANE;
    constexpr int BPLANE = 32 * PITCHB * 2;       // 8704
    constexpr int B_BUF  = (THREE ? 2 : 1) * BPLANE;
    constexpr int STAGE  = A_BUF + B_BUF;
    constexpr int ACH    = ROWS * 4;

    extern __shared__ __align__(16) char smem[];
    const uint32_t uS = smem_u32(smem);

    const int tid = threadIdx.x, lane = tid & 31, wid = tid >> 5;
    const int wm = wid >> 2, wn = wid & 3;
    const int mtile = blockIdx.x, ntile = blockIdx.y, b = blockIdx.z;
    const int n0 = ntile * 128;

    const int arow0 = (MODE == 0) ? (256 + mtile * 128) : ((MODE == 2) ? mtile * 128 : 0);
    const __half* Ag[2] = {
        (MODE == 1) ? g_W2hi : g_Ahi + (size_t)arow0 * 256,
        (MODE == 1) ? g_W2lo : g_Alo + (size_t)arow0 * 256 };
    const __half* Bg[2] = {
        ((MODE == 1) ? g_Hmhi : g_Uhi) + (size_t)b * 256 * HW + n0,
        ((MODE == 1) ? g_Hmlo : g_Ulo) + (size_t)b * 256 * HW + n0 };

    auto load_tiles = [&](int kt, int st) {
        const int k0 = kt * 32;
        const uint32_t base = uS + (uint32_t)st * STAGE;
#pragma unroll
        for (int q = tid; q < 2 * ACH; q += 256) {
            const int pl = q / ACH, qq = q % ACH;
            const int r = qq >> 2, c8 = (qq & 3) * 8;
            cpa16(base + pl * APLANE + (uint32_t)(r * PITCHA + c8) * 2,
                  Ag[pl] + (size_t)r * 256 + k0 + c8);
        }
        constexpr int nb = THREE ? 1024 : 512;
#pragma unroll
        for (int q = tid; q < nb; q += 256) {
            const int pl = q >> 9, qq = q & 511;
            const int r = qq >> 4, c8 = (qq & 15) * 8;
            cpa16(base + A_BUF + pl * BPLANE + (uint32_t)(r * PITCHB + c8) * 2,
                  Bg[pl] + (size_t)(k0 + r) * HW + c8);
        }
    };

    float acc[MI][4][4];
#pragma unroll
    for (int mi = 0; mi < MI; mi++)
#pragma unroll
        for (int ni = 0; ni < 4; ni++)
#pragma unroll
            for (int e = 0; e < 4; e++) acc[mi][ni][e] = 0.f;

    load_tiles(0, 0); CP_COMMIT();
    load_tiles(1, 1); CP_COMMIT();

#pragma unroll 1
    for (int kt = 0; kt < 8; kt++) {
        const int st = kt % 3;
        if (kt < 7) { CP_WAIT1(); } else { CP_WAIT0(); }
        __syncthreads();

        const uint32_t uAh = uS + (uint32_t)st * STAGE, uAl = uAh + APLANE;
        const uint32_t uBh = uAh + A_BUF,               uBl = uBh + BPLANE;
#pragma unroll
        for (int s = 0; s < 2; s++) {
            uint32_t ah[MI][4], al[MI][4];
            const uint32_t arow = (uint32_t)(wm * (ROWS / 2) + (lane & 15));
            const uint32_t aoff = 2u * (arow * PITCHA + s * 16 + (lane >> 4) * 8);
#pragma unroll
            for (int mi = 0; mi < MI; mi++) {
                const uint32_t o = aoff + 2u * (mi * 16 * PITCHA);
                ldsm_x4(ah[mi], uAh + o);
                ldsm_x4(al[mi], uAl + o);
            }
            const uint32_t bk = (uint32_t)(s * 16 + (lane & 15));
            const uint32_t brow = 2u * (bk * PITCHB);
#pragma unroll
            for (int ni = 0; ni < 4; ni++) {
                const uint32_t o = brow + 2u * (wn * 32 + ni * 8);
                uint32_t bh[2];
                ldsm_x2t(bh, uBh + o);
                if (THREE) {
                    uint32_t bl[2];
                    ldsm_x2t(bl, uBl + o);
#pragma unroll
                    for (int mi = 0; mi < MI; mi++) {
                        mma16816(acc[mi][ni], ah[mi], bh);
                        mma16816(acc[mi][ni], ah[mi], bl);
                        mma16816(acc[mi][ni], al[mi], bh);
                    }
                } else {
#pragma unroll
                    for (int mi = 0; mi < MI; mi++) {
                        mma16816(acc[mi][ni], ah[mi], bh);
                        mma16816(acc[mi][ni], al[mi], bh);
                    }
                }
            }
        }
        if (kt + 2 < 8) { load_tiles(kt + 2, (kt + 2) % 3); CP_COMMIT(); }
    }

    // ---------------- epilogue ----------------
    const int qr = lane >> 2, qc = (lane & 3) * 2;

    if (MODE == 1) {
#pragma unroll
        for (int mi = 0; mi < MI; mi++) {
            const int m0 = wm * 32 + mi * 16 + qr;            // < 64
            const float b0f = bias[m0], b1f = bias[m0 + 8];
            float* o0 = g_flow + ((size_t)b * 64 + m0) * HW + n0;
            float* o1 = o0 + (size_t)8 * HW;
#pragma unroll
            for (int ni = 0; ni < 4; ni++) {
                const int n = wn * 32 + ni * 8 + qc;
                float2 v0 = {acc[mi][ni][0] + b0f, acc[mi][ni][1] + b0f};
                float2 v1 = {acc[mi][ni][2] + b1f, acc[mi][ni][3] + b1f};
                *(float2*)&o0[n] = v0;
                *(float2*)&o1[n] = v1;
            }
        }
    } else if (MODE == 2) {
#pragma unroll
        for (int mi = 0; mi < MI; mi++) {
            const int c = mtile * 128 + wm * 64 + mi * 16 + qr;
            const float b0f = bias[c], b1f = bias[c + 8];
            float* o0 = g_value + ((size_t)b * 256 + c) * HW + n0;
            float* o1 = o0 + (size_t)8 * HW;
#pragma unroll
            for (int ni = 0; ni < 4; ni++) {
                const int n = wn * 32 + ni * 8 + qc;
                float2 v0 = {acc[mi][ni][0] + b0f, acc[mi][ni][1] + b0f};
                float2 v1 = {acc[mi][ni][2] + b1f, acc[mi][ni][3] + b1f};
                *(float2*)&o0[n] = v0;
                *(float2*)&o1[n] = v1;
            }
        }
    } else {
#pragma unroll
        for (int mi = 0; mi < MI; mi++) {
            const int c = mtile * 128 + wm * 64 + mi * 16 + qr;
            const float b0f = bias[c], b1f = bias[c + 8];
            __half* oh0 = g_Hmhi + ((size_t)b * 256 + c) * HW + n0;
            __half* ol0 = g_Hmlo + ((size_t)b * 256 + c) * HW + n0;
#pragma unroll
            for (int ni = 0; ni < 4; ni++) {
                const int n = wn * 32 + ni * 8 + qc;
#pragma unroll
                for (int hf = 0; hf < 2; hf++) {
                    const float bb = hf ? b1f : b0f;
                    float x0 = fmaxf(acc[mi][ni][hf * 2 + 0] + bb, 0.f);
                    float x1 = fmaxf(acc[mi][ni][hf * 2 + 1] + bb, 0.f);
                    __half h0 = __float2half_rn(x0);
                    __half h1 = __float2half_rn(x1);
                    union { __half v[2]; uint32_t q; } hh, ll;
                    hh.v[0] = h0; hh.v[1] = h1;
                    ll.v[0] = __float2half_rn(x0 - __half2float(h0));
                    ll.v[1] = __float2half_rn(x1 - __half2float(h1));
                    const size_t off = (size_t)(hf * 8) * HW + n;
                    *reinterpret_cast<uint32_t*>(oh0 + off) = hh.q;
                    *reinterpret_cast<uint32_t*>(ol0 + off) = ll.q;
                }
            }
        }
    }
}

// ---------------------------------------------------------------------------
__global__ __launch_bounds__(128)
void warp_gather_kernel(float* __restrict__ out)
{
    const int x = threadIdx.x, y = blockIdx.x, bh = blockIdx.y;
    const int b = bh >> 5, head = bh & 31;

    const float* fb = g_flow + ((size_t)b * 64 + head * 2) * HW + y * WDIM + x;
    const float fx = fb[0];
    const float fy = fb[HW];

    const float gx = fmaf((float)x, 2.f / 127.f, -1.f) + fx;
    const float gy = fmaf((float)y, 2.f / 127.f, -1.f) + fy;
    const float ix = (gx + 1.f) * 63.5f;
    const float iy = (gy + 1.f) * 63.5f;

    const float x0f = floorf(ix), y0f = floorf(iy);
    const float dx = ix - x0f, dy = iy - y0f;
    const int x0 = (int)x0f, y0 = (int)y0f;
    const int x1 = x0 + 1,   y1 = y0 + 1;

    const bool vx0 = (x0 >= 0) & (x0 < WDIM);
    const bool vx1 = (x1 >= 0) & (x1 < WDIM);
    const bool vy0 = (y0 >= 0) & (y0 < WDIM);
    const bool vy1 = (y1 >= 0) & (y1 < WDIM);

    const int x0c = min(max(x0, 0), WDIM - 1);
    const int x1c = min(max(x1, 0), WDIM - 1);
    const int y0c = min(max(y0, 0), WDIM - 1);
    const int y1c = min(max(y1, 0), WDIM - 1);

    const float w00 = (1.f - dx) * (1.f - dy) * (float)(vx0 & vy0);
    const float w01 = dx * (1.f - dy)         * (float)(vx1 & vy0);
    const float w10 = (1.f - dx) * dy         * (float)(vx0 & vy1);
    const float w11 = dx * dy                 * (float)(vx1 & vy1);

    const int p00 = y0c * WDIM + x0c;
    const int p01 = y0c * WDIM + x1c;
    const int p10 = y1c * WDIM + x0c;
    const int p11 = y1c * WDIM + x1c;

    const float* vb = g_value + ((size_t)b * 256 + head * 8) * HW;
    float* ob = out + ((size_t)b * 256 + head * 8) * HW + y * WDIM + x;

#pragma unroll
    for (int ci = 0; ci < 8; ci++) {
        const float* v = vb + (size_t)ci * HW;
        ob[(size_t)ci * HW] = w00 * v[p00] + w01 * v[p01] + w10 * v[p10] + w11 * v[p11];
    }
}

// ---------------------------------------------------------------------------
extern "C" void kernel_launch(void* const* d_in, const int* in_sizes, int n_in,
                              void* d_out, int out_size)
{
    const float* u  = (const float*)d_in[0];
    const float* w1 = (const float*)d_in[1];
    const float* b1 = (const float*)d_in[2];
    const float* w2 = (const float*)d_in[3];
    const float* b2 = (const float*)d_in[4];
    const float* wv = (const float*)d_in[5];
    const float* bv = (const float*)d_in[6];
    float* out = (float*)d_out;

    constexpr int SM_H = 3 * (2 * 2 * 128 * PITCHA + 2 * 2 * 32 * PITCHB);  // 113664
    constexpr int SM_F = 3 * (2 * 2 * 64  * PITCHA + 2 * 2 * 32 * PITCHB);  // 82944
    constexpr int SM_V = 3 * (2 * 2 * 128 * PITCHA + 1 * 2 * 32 * PITCHB);  // 87552

    static cudaStream_t s2;
    static cudaEvent_t evU, evV;
    static bool init = false;
    if (!init) {
        cudaFuncSetAttribute(gemm_kernel<0>, cudaFuncAttributeMaxDynamicSharedMemorySize, SM_H);
        cudaFuncSetAttribute(gemm_kernel<1>, cudaFuncAttributeMaxDynamicSharedMemorySize, SM_F);
        cudaFuncSetAttribute(gemm_kernel<2>, cudaFuncAttributeMaxDynamicSharedMemorySize, SM_V);
        cudaStreamCreateWithFlags(&s2, cudaStreamNonBlocking);
        cudaEventCreateWithFlags(&evU, cudaEventDisableTiming);
        cudaEventCreateWithFlags(&evV, cudaEventDisableTiming);
        init = true;
    }

    prep_weights<<<640, 256>>>(w1, wv, w2);
    convert_u<<<8192, 256>>>((const float4*)u);

    // fork: value GEMM on s2, h->flow chain on main stream
    cudaEventRecord(evU, 0);
    cudaStreamWaitEvent(s2, evU, 0);
    gemm_kernel<2><<<dim3(2, 128, NB), 256, SM_V, s2>>>(bv);
    cudaEventRecord(evV, s2);

    gemm_kernel<0><<<dim3(2, 128, NB), 256, SM_H>>>(b1);
    gemm_kernel<1><<<dim3(1, 128, NB), 256, SM_F>>>(b2);

    // join, then gather
    cudaStreamWaitEvent(0, evV, 0);
    warp_gather_kernel<<<dim3(128, 128), 128>>>(out);
}